// round 1
// baseline (speedup 1.0000x reference)
#include <cuda_runtime.h>
#include <math.h>

// ---------------- problem constants ----------------
#define TN   131072      // local tx nodes
#define ELN  524288      // local edges
#define NNODE 50000      // global contract nodes
#define EGN  400000      // global edges
#define BB   8192        // batch of contracts
#define HH   128         // hidden dim
#define FGN  7           // global feat dim
#define HCN  64          // classifier hidden
#define CC   2           // classes

#define CDIV(a,b) (((a)+(b)-1)/(b))

// ---------------- scratch (device globals; no allocation allowed) ----------------
__device__ float    g_h   [TN*HH];       // local node features
__device__ float    g_z   [TN*HH];       // z = h @ W
__device__ float    g_acc [TN*HH];       // GAT output accumulator
__device__ float    g_ssrc[TN*4];
__device__ float    g_sdst[TN*4];
__device__ float    g_esc [ELN*4];       // edge scores -> exp()
__device__ unsigned g_maxi[TN*4];
__device__ float    g_den [TN*4];
__device__ float    g_ce  [4];
__device__ float    g_emb [BB*HH];
__device__ float    g_cnt [BB];
__device__ float    g_cat [BB*(HH+FGN)];
__device__ float    g_tmp [BB*HH];
__device__ float    g_fused[BB*HH];
__device__ float    g_gx  [NNODE*HH];
__device__ float    g_gz  [NNODE*HH];
__device__ float    g_gacc[NNODE*HH];
__device__ float    g_gesc[EGN*2];

// ---------------- helpers ----------------
__device__ __forceinline__ unsigned fkey(float f) {
    unsigned u = __float_as_uint(f);
    return (u & 0x80000000u) ? ~u : (u | 0x80000000u);
}
__device__ __forceinline__ float funkey(unsigned k) {
    unsigned u = (k & 0x80000000u) ? (k & 0x7fffffffu) : ~k;
    return __uint_as_float(u);
}

// ---------------- GEMM: C[M,128] = A[M,K] @ W[K,128] (+bias) ----------------
// 256 threads, tile 64x128, K-tile 32, 4x8 micro-tile per thread.
__global__ void gemm128(const float* __restrict__ A, const float* __restrict__ W,
                        const float* __restrict__ bias, float* __restrict__ C,
                        int M, int K) {
    __shared__ float As[32][65];
    __shared__ float Ws[32][132];
    const int bm  = blockIdx.x * 64;
    const int tid = threadIdx.x;
    const int tc  = (tid & 15) * 8;
    const int tr  = (tid >> 4) * 4;
    float acc[4][8];
#pragma unroll
    for (int i = 0; i < 4; i++)
#pragma unroll
        for (int j = 0; j < 8; j++) acc[i][j] = 0.f;

    for (int k0 = 0; k0 < K; k0 += 32) {
        for (int i = tid; i < 64 * 32; i += 256) {
            int m = i >> 5, kk = i & 31;
            int gr = bm + m, gk = k0 + kk;
            As[kk][m] = (gr < M && gk < K) ? A[(size_t)gr * K + gk] : 0.f;
        }
        for (int i = tid; i < 32 * 128; i += 256) {
            int kk = i >> 7, n = i & 127;
            int gk = k0 + kk;
            Ws[kk][n] = (gk < K) ? W[gk * 128 + n] : 0.f;
        }
        __syncthreads();
#pragma unroll
        for (int kk = 0; kk < 32; kk++) {
            float a0 = As[kk][tr], a1 = As[kk][tr + 1];
            float a2 = As[kk][tr + 2], a3 = As[kk][tr + 3];
#pragma unroll
            for (int j = 0; j < 8; j++) {
                float w = Ws[kk][tc + j];
                acc[0][j] += a0 * w; acc[1][j] += a1 * w;
                acc[2][j] += a2 * w; acc[3][j] += a3 * w;
            }
        }
        __syncthreads();
    }
#pragma unroll
    for (int i = 0; i < 4; i++) {
        int gr = bm + tr + i;
        if (gr < M) {
#pragma unroll
            for (int j = 0; j < 8; j++) {
                float v = acc[i][j];
                if (bias) v += bias[tc + j];
                C[(size_t)gr * 128 + tc + j] = v;
            }
        }
    }
}

// ---------------- per-node attention scores ----------------
template <int NH, int HD>
__global__ void scores_k(const float* __restrict__ z, const float* __restrict__ as_,
                         const float* __restrict__ ad_, float* __restrict__ ssrc,
                         float* __restrict__ sdst, int n) {
    int i = blockIdx.x * blockDim.x + threadIdx.x;
    if (i >= n * NH) return;
    int node = i / NH, h = i % NH;
    const float* zp = z + (size_t)node * HH + h * HD;
    const float* ap = as_ + h * HD;
    const float* dp = ad_ + h * HD;
    float s = 0.f, t = 0.f;
#pragma unroll
    for (int d = 0; d < HD; d++) { float zv = zp[d]; s += zv * ap[d]; t += zv * dp[d]; }
    ssrc[i] = s; sdst[i] = t;
}

// per-head edge-attr constant: ce[h] = sum_d eW[h*32+d] * ae[h*32+d]
__global__ void ce_k(const float* __restrict__ eW, const float* __restrict__ ae,
                     float* __restrict__ ce) {
    int h = threadIdx.x;
    if (h >= 4) return;
    float s = 0.f;
    for (int d = 0; d < 32; d++) s += eW[h * 32 + d] * ae[h * 32 + d];
    ce[h] = s;
}

// ---------------- edge pass 1: score + leaky + atomicMax ----------------
template <int NH>
__global__ void epass1(const int* __restrict__ src, const int* __restrict__ dst,
                       const float* __restrict__ eattr, const float* __restrict__ ce,
                       const float* __restrict__ ssrc, const float* __restrict__ sdst,
                       float* __restrict__ score, unsigned* __restrict__ maxi, int E) {
    int i = blockIdx.x * blockDim.x + threadIdx.x;
    if (i >= E * NH) return;
    int e = i / NH, h = i % NH;
    int s = src[e], d = dst[e];
    float sc = ssrc[s * NH + h] + sdst[d * NH + h];
    if (eattr) sc += eattr[e] * ce[h];
    sc = sc > 0.f ? sc : 0.2f * sc;
    score[i] = sc;
    atomicMax(&maxi[d * NH + h], fkey(sc));
}

// ---------------- edge pass 2: exp + atomic denominator ----------------
template <int NH>
__global__ void epass2(const int* __restrict__ dst, float* __restrict__ score,
                       const unsigned* __restrict__ maxi, float* __restrict__ den, int E) {
    int i = blockIdx.x * blockDim.x + threadIdx.x;
    if (i >= E * NH) return;
    int e = i / NH, h = i % NH;
    int d = dst[e];
    float m = funkey(maxi[d * NH + h]);
    float ex = expf(score[i] - m);
    score[i] = ex;
    atomicAdd(&den[d * NH + h], ex);
}

// ---------------- edge pass 3: weighted scatter ----------------
template <int NH, int HD>
__global__ void epass3(const int* __restrict__ src, const int* __restrict__ dst,
                       const float* __restrict__ ex, const float* __restrict__ den,
                       const float* __restrict__ z, float* __restrict__ acc, int E) {
    int i = blockIdx.x * blockDim.x + threadIdx.x;
    if (i >= E * HH) return;
    int e = i >> 7, c = i & 127;
    int h = c / HD;
    int d = dst[e], s = src[e];
    float a = ex[e * NH + h] / fmaxf(den[d * NH + h], 1e-16f);
    atomicAdd(&acc[(size_t)d * HH + c], a * z[(size_t)s * HH + c]);
}

// ---------------- residual + bias + ELU ----------------
__global__ void update_k(float* __restrict__ h, const float* __restrict__ acc,
                         const float* __restrict__ b, int n) {
    int i = blockIdx.x * blockDim.x + threadIdx.x;
    if (i >= n * HH) return;
    float x = h[i] + acc[i] + b[i & 127];
    h[i] = x > 0.f ? x : expf(x) - 1.f;
}

// ---------------- mean pooling ----------------
__global__ void pool_add(const float* __restrict__ h, const int* __restrict__ nb,
                         float* __restrict__ emb) {
    int i = blockIdx.x * blockDim.x + threadIdx.x;
    if (i >= TN * HH) return;
    atomicAdd(&emb[(size_t)nb[i >> 7] * HH + (i & 127)], h[i]);
}
__global__ void pool_cnt(const int* __restrict__ nb, float* __restrict__ cnt) {
    int i = blockIdx.x * blockDim.x + threadIdx.x;
    if (i >= TN) return;
    atomicAdd(&cnt[nb[i]], 1.f);
}
__global__ void pool_fin(float* __restrict__ emb, const float* __restrict__ cnt) {
    int i = blockIdx.x * blockDim.x + threadIdx.x;
    if (i >= BB * HH) return;
    emb[i] /= fmaxf(cnt[i >> 7], 1.f);
}

// ---------------- concat [emb | gf[cid]] ----------------
__global__ void concat_k(const float* __restrict__ emb, const float* __restrict__ gf,
                         const int* __restrict__ cid, float* __restrict__ cat) {
    int i = blockIdx.x * blockDim.x + threadIdx.x;
    if (i >= BB * (HH + FGN)) return;
    int b = i / (HH + FGN), j = i % (HH + FGN);
    cat[i] = (j < HH) ? emb[(size_t)b * HH + j]
                      : gf[(size_t)cid[b] * FGN + (j - HH)];
}

// ---------------- LayerNorm(128) + ReLU ----------------
__global__ void ln_relu_k(const float* __restrict__ X, const float* __restrict__ g,
                          const float* __restrict__ be, float* __restrict__ Y) {
    int row = blockIdx.x, t = threadIdx.x;
    float v = X[(size_t)row * HH + t];
    __shared__ float red[HH];
    red[t] = v; __syncthreads();
    for (int s = 64; s > 0; s >>= 1) { if (t < s) red[t] += red[t + s]; __syncthreads(); }
    float mean = red[0] / 128.f;
    __syncthreads();
    float dv = v - mean;
    red[t] = dv * dv; __syncthreads();
    for (int s = 64; s > 0; s >>= 1) { if (t < s) red[t] += red[t + s]; __syncthreads(); }
    float var = red[0] / 128.f;
    float y = dv * rsqrtf(var + 1e-5f) * g[t] + be[t];
    Y[(size_t)row * HH + t] = fmaxf(y, 0.f);
}

// ---------------- scatter fused batch embeddings into gx ----------------
__global__ void scatter_k(float* __restrict__ gx, const float* __restrict__ fused,
                          const int* __restrict__ cid) {
    int i = blockIdx.x * blockDim.x + threadIdx.x;
    if (i >= BB * HH) return;
    int b = i >> 7;
    gx[(size_t)cid[b] * HH + (i & 127)] = fused[i];
}

// ---------------- classifier: gather + 128->64 relu -> 64->2 ----------------
__global__ void classifier_k(const float* __restrict__ gx, const int* __restrict__ cid,
                             const float* __restrict__ W1, const float* __restrict__ b1,
                             const float* __restrict__ W2, const float* __restrict__ b2,
                             float* __restrict__ out) {
    int b = blockIdx.x, t = threadIdx.x;  // 64 threads
    __shared__ float row[HH];
    __shared__ float hc[HCN];
    const float* srcp = gx + (size_t)cid[b] * HH;
    row[t] = srcp[t];
    row[t + 64] = srcp[t + 64];
    __syncthreads();
    float s = b1[t];
#pragma unroll
    for (int k = 0; k < HH; k++) s += row[k] * W1[k * HCN + t];
    hc[t] = fmaxf(s, 0.f);
    __syncthreads();
    if (t < CC) {
        float s2 = b2[t];
#pragma unroll
        for (int k = 0; k < HCN; k++) s2 += hc[k] * W2[k * CC + t];
        out[b * CC + t] = s2;
    }
}

// ---------------- launch ----------------
extern "C" void kernel_launch(void* const* d_in, const int* in_sizes, int n_in,
                              void* d_out, int out_size) {
    const float* x_local    = (const float*)d_in[0];
    const float* eattr      = (const float*)d_in[1];
    const float* gfeat      = (const float*)d_in[2];
    const float* loc_in_W   = (const float*)d_in[3];
    const float* loc_in_b   = (const float*)d_in[4];
    const float* loc_W      = (const float*)d_in[5];
    const float* loc_asrc   = (const float*)d_in[6];
    const float* loc_adst   = (const float*)d_in[7];
    const float* loc_eW     = (const float*)d_in[8];
    const float* loc_ae     = (const float*)d_in[9];
    const float* loc_b      = (const float*)d_in[10];
    const float* fp_W       = (const float*)d_in[11];
    const float* fp_b       = (const float*)d_in[12];
    const float* fp_g       = (const float*)d_in[13];
    const float* fp_beta    = (const float*)d_in[14];
    const float* gp_W       = (const float*)d_in[15];
    const float* gp_b       = (const float*)d_in[16];
    const float* gp_g       = (const float*)d_in[17];
    const float* gp_beta    = (const float*)d_in[18];
    const float* glob_W     = (const float*)d_in[19];
    const float* glob_asrc  = (const float*)d_in[20];
    const float* glob_adst  = (const float*)d_in[21];
    const float* glob_b     = (const float*)d_in[22];
    const float* cls_W1     = (const float*)d_in[23];
    const float* cls_b1     = (const float*)d_in[24];
    const float* cls_W2     = (const float*)d_in[25];
    const float* cls_b2     = (const float*)d_in[26];
    const int*   eil        = (const int*)d_in[27];   // [2, EL]
    const int*   node_batch = (const int*)d_in[28];
    const int*   cid        = (const int*)d_in[29];
    const int*   gei        = (const int*)d_in[30];   // [2, EG]

    const int* lsrc = eil;
    const int* ldst = eil + ELN;
    const int* gsrc = gei;
    const int* gdst = gei + EGN;

    float *p_h, *p_z, *p_acc, *p_ssrc, *p_sdst, *p_esc, *p_den, *p_ce;
    float *p_emb, *p_cnt, *p_cat, *p_tmp, *p_fused, *p_gx, *p_gz, *p_gacc, *p_gesc;
    unsigned* p_maxi;
    cudaGetSymbolAddress((void**)&p_h, g_h);
    cudaGetSymbolAddress((void**)&p_z, g_z);
    cudaGetSymbolAddress((void**)&p_acc, g_acc);
    cudaGetSymbolAddress((void**)&p_ssrc, g_ssrc);
    cudaGetSymbolAddress((void**)&p_sdst, g_sdst);
    cudaGetSymbolAddress((void**)&p_esc, g_esc);
    cudaGetSymbolAddress((void**)&p_maxi, g_maxi);
    cudaGetSymbolAddress((void**)&p_den, g_den);
    cudaGetSymbolAddress((void**)&p_ce, g_ce);
    cudaGetSymbolAddress((void**)&p_emb, g_emb);
    cudaGetSymbolAddress((void**)&p_cnt, g_cnt);
    cudaGetSymbolAddress((void**)&p_cat, g_cat);
    cudaGetSymbolAddress((void**)&p_tmp, g_tmp);
    cudaGetSymbolAddress((void**)&p_fused, g_fused);
    cudaGetSymbolAddress((void**)&p_gx, g_gx);
    cudaGetSymbolAddress((void**)&p_gz, g_gz);
    cudaGetSymbolAddress((void**)&p_gacc, g_gacc);
    cudaGetSymbolAddress((void**)&p_gesc, g_gesc);

    // ---- local encoder: input projection ----
    gemm128<<<CDIV(TN, 64), 256>>>(x_local, loc_in_W, loc_in_b, p_h, TN, 4);

    // ---- 2x local GATConv ----
    for (int l = 0; l < 2; l++) {
        gemm128<<<CDIV(TN, 64), 256>>>(p_h, loc_W + l * HH * HH, nullptr, p_z, TN, HH);
        scores_k<4, 32><<<CDIV(TN * 4, 256), 256>>>(p_z, loc_asrc + l * HH,
                                                    loc_adst + l * HH, p_ssrc, p_sdst, TN);
        cudaMemsetAsync(p_maxi, 0, (size_t)TN * 4 * sizeof(unsigned));
        cudaMemsetAsync(p_den, 0, (size_t)TN * 4 * sizeof(float));
        ce_k<<<1, 4>>>(loc_eW + l * HH, loc_ae + l * HH, p_ce);
        epass1<4><<<CDIV(ELN * 4, 256), 256>>>(lsrc, ldst, eattr, p_ce, p_ssrc, p_sdst,
                                               p_esc, p_maxi, ELN);
        epass2<4><<<CDIV(ELN * 4, 256), 256>>>(ldst, p_esc, p_maxi, p_den, ELN);
        cudaMemsetAsync(p_acc, 0, (size_t)TN * HH * sizeof(float));
        epass3<4, 32><<<CDIV(ELN * HH, 256), 256>>>(lsrc, ldst, p_esc, p_den, p_z, p_acc, ELN);
        update_k<<<CDIV(TN * HH, 256), 256>>>(p_h, p_acc, loc_b + l * HH, TN);
    }

    // ---- contract mean pooling ----
    cudaMemsetAsync(p_emb, 0, (size_t)BB * HH * sizeof(float));
    cudaMemsetAsync(p_cnt, 0, (size_t)BB * sizeof(float));
    pool_add<<<CDIV(TN * HH, 256), 256>>>(p_h, node_batch, p_emb);
    pool_cnt<<<CDIV(TN, 256), 256>>>(node_batch, p_cnt);
    pool_fin<<<CDIV(BB * HH, 256), 256>>>(p_emb, p_cnt);

    // ---- fused MLP (concat -> linear -> LN -> ReLU) ----
    concat_k<<<CDIV(BB * (HH + FGN), 256), 256>>>(p_emb, gfeat, cid, p_cat);
    gemm128<<<CDIV(BB, 64), 256>>>(p_cat, fp_W, fp_b, p_tmp, BB, HH + FGN);
    ln_relu_k<<<BB, HH>>>(p_tmp, fp_g, fp_beta, p_fused);

    // ---- global projection for all N nodes, then scatter fused in ----
    gemm128<<<CDIV(NNODE, 64), 256>>>(gfeat, gp_W, gp_b, p_gz, NNODE, FGN);
    ln_relu_k<<<NNODE, HH>>>(p_gz, gp_g, gp_beta, p_gx);
    scatter_k<<<CDIV(BB * HH, 256), 256>>>(p_gx, p_fused, cid);

    // ---- 2x global GATConv ----
    for (int l = 0; l < 2; l++) {
        gemm128<<<CDIV(NNODE, 64), 256>>>(p_gx, glob_W + l * HH * HH, nullptr, p_gz, NNODE, HH);
        scores_k<2, 64><<<CDIV(NNODE * 2, 256), 256>>>(p_gz, glob_asrc + l * HH,
                                                       glob_adst + l * HH, p_ssrc, p_sdst, NNODE);
        cudaMemsetAsync(p_maxi, 0, (size_t)NNODE * 2 * sizeof(unsigned));
        cudaMemsetAsync(p_den, 0, (size_t)NNODE * 2 * sizeof(float));
        epass1<2><<<CDIV(EGN * 2, 256), 256>>>(gsrc, gdst, (const float*)nullptr,
                                               (const float*)nullptr, p_ssrc, p_sdst,
                                               p_gesc, p_maxi, EGN);
        epass2<2><<<CDIV(EGN * 2, 256), 256>>>(gdst, p_gesc, p_maxi, p_den, EGN);
        cudaMemsetAsync(p_gacc, 0, (size_t)NNODE * HH * sizeof(float));
        epass3<2, 64><<<CDIV(EGN * HH, 256), 256>>>(gsrc, gdst, p_gesc, p_den, p_gz, p_gacc, EGN);
        update_k<<<CDIV(NNODE * HH, 256), 256>>>(p_gx, p_gacc, glob_b + l * HH, NNODE);
    }

    // ---- classifier ----
    classifier_k<<<BB, 64>>>(p_gx, cid, cls_W1, cls_b1, cls_W2, cls_b2, (float*)d_out);
}

// round 2
// speedup vs baseline: 1.6069x; 1.6069x over previous
#include <cuda_runtime.h>
#include <math.h>

// ---------------- problem constants ----------------
#define TN    131072     // local tx nodes
#define ELN   524288     // local edges
#define NNODE 50000      // global contract nodes
#define EGN   400000     // global edges
#define BB    8192       // batch of contracts
#define HH    128        // hidden dim
#define FGN   7          // global feat dim
#define HCN   64         // classifier hidden
#define CC    2          // classes

#define CDIV(a,b) (((a)+(b)-1)/(b))

// ---------------- scratch (device globals) ----------------
__device__ float g_h   [TN*HH];
__device__ float g_z   [TN*HH];
__device__ float g_acc [TN*HH];
__device__ float g_ssrc[TN*4];
__device__ float g_sdst[TN*4];
__device__ float g_esc [ELN*4];
__device__ float g_den [TN*4];
__device__ float g_ce  [4];
__device__ float g_emb [BB*HH];
__device__ float g_cnt [BB];
__device__ float g_cat [BB*(HH+FGN)];
__device__ float g_tmp [BB*HH];
__device__ float g_fused[BB*HH];
__device__ float g_gx  [NNODE*HH];
__device__ float g_gz  [NNODE*HH];
__device__ float g_gacc[NNODE*HH];
__device__ float g_gesc[EGN*2];
__device__ float g_gden[NNODE*2];

// ---------------- vector reductions (sm_90+) ----------------
__device__ __forceinline__ void red_add_v4(float* a, float x, float y, float z, float w) {
    asm volatile("red.global.add.v4.f32 [%0], {%1,%2,%3,%4};"
                 :: "l"(a), "f"(x), "f"(y), "f"(z), "f"(w) : "memory");
}
__device__ __forceinline__ void red_add_v2(float* a, float x, float y) {
    asm volatile("red.global.add.v2.f32 [%0], {%1,%2};"
                 :: "l"(a), "f"(x), "f"(y) : "memory");
}

// ---------------- GEMM: C[M,128] = A[M,K] @ W[K,128] (+bias) ----------------
// 128x128 tile, 256 threads, 8x8 micro-tile, BK=16 double buffered.
#define BKK 16
#define APAD 132
#define WPAD 132
__global__ __launch_bounds__(256, 2)
void gemm_tile(const float* __restrict__ A, const float* __restrict__ W,
               const float* __restrict__ bias, float* __restrict__ C,
               int M, int K) {
    __shared__ float As[2][BKK * APAD];   // [kk][m]
    __shared__ float Ws[2][BKK * WPAD];   // [kk][n]
    const int bm  = blockIdx.x * 128;
    const int tid = threadIdx.x;
    const int tr  = (tid >> 4) * 8;
    const int tc  = (tid & 15) * 8;
    float acc[8][8];
#pragma unroll
    for (int x = 0; x < 8; x++)
#pragma unroll
        for (int y = 0; y < 8; y++) acc[x][y] = 0.f;

    const int nk = CDIV(K, BKK);

    // prologue load tile 0
    {
        int k0 = 0;
#pragma unroll
        for (int i = tid; i < 128 * BKK; i += 256) {
            int m = i >> 4, kk = i & (BKK - 1);
            int gr = bm + m, gk = k0 + kk;
            As[0][kk * APAD + m] = (gr < M && gk < K) ? A[(size_t)gr * K + gk] : 0.f;
        }
#pragma unroll
        for (int i = tid; i < BKK * 128; i += 256) {
            int kk = i >> 7, n = i & 127;
            int gk = k0 + kk;
            Ws[0][kk * WPAD + n] = (gk < K) ? W[gk * 128 + n] : 0.f;
        }
    }
    __syncthreads();

    for (int t = 0; t < nk; t++) {
        int cur = t & 1;
        if (t + 1 < nk) {
            int k0 = (t + 1) * BKK;
            int nxt = cur ^ 1;
#pragma unroll
            for (int i = tid; i < 128 * BKK; i += 256) {
                int m = i >> 4, kk = i & (BKK - 1);
                int gr = bm + m, gk = k0 + kk;
                As[nxt][kk * APAD + m] = (gr < M && gk < K) ? A[(size_t)gr * K + gk] : 0.f;
            }
#pragma unroll
            for (int i = tid; i < BKK * 128; i += 256) {
                int kk = i >> 7, n = i & 127;
                int gk = k0 + kk;
                Ws[nxt][kk * WPAD + n] = (gk < K) ? W[gk * 128 + n] : 0.f;
            }
        }
#pragma unroll
        for (int kk = 0; kk < BKK; kk++) {
            float a[8], w[8];
#pragma unroll
            for (int x = 0; x < 8; x++) a[x] = As[cur][kk * APAD + tr + x];
#pragma unroll
            for (int y = 0; y < 8; y++) w[y] = Ws[cur][kk * WPAD + tc + y];
#pragma unroll
            for (int x = 0; x < 8; x++)
#pragma unroll
                for (int y = 0; y < 8; y++) acc[x][y] += a[x] * w[y];
        }
        __syncthreads();
    }

#pragma unroll
    for (int x = 0; x < 8; x++) {
        int gr = bm + tr + x;
        if (gr < M) {
#pragma unroll
            for (int y = 0; y < 8; y++) {
                float v = acc[x][y];
                if (bias) v += bias[tc + y];
                C[(size_t)gr * 128 + tc + y] = v;
            }
        }
    }
}

// ---------------- per-node attention scores ----------------
template <int NH, int HD>
__global__ void scores_k(const float* __restrict__ z, const float* __restrict__ as_,
                         const float* __restrict__ ad_, float* __restrict__ ssrc,
                         float* __restrict__ sdst, int n) {
    int i = blockIdx.x * blockDim.x + threadIdx.x;
    if (i >= n * NH) return;
    int node = i / NH, h = i % NH;
    const float* zp = z + (size_t)node * HH + h * HD;
    const float* ap = as_ + h * HD;
    const float* dp = ad_ + h * HD;
    float s = 0.f, t = 0.f;
#pragma unroll
    for (int d = 0; d < HD; d++) { float zv = zp[d]; s += zv * ap[d]; t += zv * dp[d]; }
    ssrc[i] = s; sdst[i] = t;
}

__global__ void ce_k(const float* __restrict__ eW, const float* __restrict__ ae,
                     float* __restrict__ ce) {
    int h = threadIdx.x;
    if (h >= 4) return;
    float s = 0.f;
    for (int d = 0; d < 32; d++) s += eW[h * 32 + d] * ae[h * 32 + d];
    ce[h] = s;
}

// ---------------- merged edge pass: score+leaky+exp+denominator ----------------
// (no max-subtraction: softmax is shift-invariant, scores are O(1))
__global__ void epass12_l(const int* __restrict__ src, const int* __restrict__ dst,
                          const float* __restrict__ eattr, const float* __restrict__ ce,
                          const float* __restrict__ ssrc, const float* __restrict__ sdst,
                          float* __restrict__ ex, float* __restrict__ den, int E) {
    int e = blockIdx.x * blockDim.x + threadIdx.x;
    if (e >= E) return;
    int s = src[e], d = dst[e];
    float4 ss = *(const float4*)(ssrc + (size_t)s * 4);
    float4 sd = *(const float4*)(sdst + (size_t)d * 4);
    float ea = eattr[e];
    float c0 = ss.x + sd.x + ea * ce[0];
    float c1 = ss.y + sd.y + ea * ce[1];
    float c2 = ss.z + sd.z + ea * ce[2];
    float c3 = ss.w + sd.w + ea * ce[3];
    c0 = c0 > 0.f ? c0 : 0.2f * c0;  c1 = c1 > 0.f ? c1 : 0.2f * c1;
    c2 = c2 > 0.f ? c2 : 0.2f * c2;  c3 = c3 > 0.f ? c3 : 0.2f * c3;
    float e0 = expf(c0), e1 = expf(c1), e2 = expf(c2), e3 = expf(c3);
    *(float4*)(ex + (size_t)e * 4) = make_float4(e0, e1, e2, e3);
    red_add_v4(den + (size_t)d * 4, e0, e1, e2, e3);
}

__global__ void epass12_g(const int* __restrict__ src, const int* __restrict__ dst,
                          const float* __restrict__ ssrc, const float* __restrict__ sdst,
                          float* __restrict__ ex, float* __restrict__ den, int E) {
    int e = blockIdx.x * blockDim.x + threadIdx.x;
    if (e >= E) return;
    int s = src[e], d = dst[e];
    float2 ss = *(const float2*)(ssrc + (size_t)s * 2);
    float2 sd = *(const float2*)(sdst + (size_t)d * 2);
    float c0 = ss.x + sd.x, c1 = ss.y + sd.y;
    c0 = c0 > 0.f ? c0 : 0.2f * c0;  c1 = c1 > 0.f ? c1 : 0.2f * c1;
    float e0 = expf(c0), e1 = expf(c1);
    *(float2*)(ex + (size_t)e * 2) = make_float2(e0, e1);
    red_add_v2(den + (size_t)d * 2, e0, e1);
}

// ---------------- normalize ex -> alpha ----------------
__global__ void enorm_l(const int* __restrict__ dst, float* __restrict__ ex,
                        const float* __restrict__ den, int E) {
    int e = blockIdx.x * blockDim.x + threadIdx.x;
    if (e >= E) return;
    int d = dst[e];
    float4 dn = *(const float4*)(den + (size_t)d * 4);
    float4 v = *(float4*)(ex + (size_t)e * 4);
    v.x /= fmaxf(dn.x, 1e-16f); v.y /= fmaxf(dn.y, 1e-16f);
    v.z /= fmaxf(dn.z, 1e-16f); v.w /= fmaxf(dn.w, 1e-16f);
    *(float4*)(ex + (size_t)e * 4) = v;
}
__global__ void enorm_g(const int* __restrict__ dst, float* __restrict__ ex,
                        const float* __restrict__ den, int E) {
    int e = blockIdx.x * blockDim.x + threadIdx.x;
    if (e >= E) return;
    int d = dst[e];
    float2 dn = *(const float2*)(den + (size_t)d * 2);
    float2 v = *(float2*)(ex + (size_t)e * 2);
    v.x /= fmaxf(dn.x, 1e-16f); v.y /= fmaxf(dn.y, 1e-16f);
    *(float2*)(ex + (size_t)e * 2) = v;
}

// ---------------- weighted scatter (vector reductions) ----------------
// one thread per (edge, 4 channels). 32 thread-groups per edge.
template <int NH, int HD>
__global__ void epass3(const int* __restrict__ src, const int* __restrict__ dst,
                       const float* __restrict__ alpha, const float* __restrict__ z,
                       float* __restrict__ acc, int E) {
    long long i = (long long)blockIdx.x * blockDim.x + threadIdx.x;
    if (i >= (long long)E * 32) return;
    int e = (int)(i >> 5), q = (int)(i & 31);
    int c = q * 4;
    int h = c / HD;
    int s = src[e], d = dst[e];
    float a = alpha[(size_t)e * NH + h];
    float4 zv = *(const float4*)(z + (size_t)s * HH + c);
    red_add_v4(acc + (size_t)d * HH + c, a * zv.x, a * zv.y, a * zv.z, a * zv.w);
}

// ---------------- acc init (residual + bias), ELU finish ----------------
__global__ void accinit_k(const float* __restrict__ h, const float* __restrict__ b,
                          float* __restrict__ acc, int n) {
    int i = blockIdx.x * blockDim.x + threadIdx.x;
    if (i >= n * HH) return;
    acc[i] = h[i] + b[i & 127];
}
__global__ void elu_k(const float* __restrict__ acc, float* __restrict__ h, int n) {
    int i = blockIdx.x * blockDim.x + threadIdx.x;
    if (i >= n * HH) return;
    float x = acc[i];
    h[i] = x > 0.f ? x : expf(x) - 1.f;
}

// ---------------- mean pooling ----------------
__global__ void pool_add(const float* __restrict__ h, const int* __restrict__ nb,
                         float* __restrict__ emb) {
    long long i = (long long)blockIdx.x * blockDim.x + threadIdx.x;
    if (i >= (long long)TN * 32) return;
    int node = (int)(i >> 5), c = (int)(i & 31) * 4;
    int b = nb[node];
    float4 v = *(const float4*)(h + (size_t)node * HH + c);
    red_add_v4(emb + (size_t)b * HH + c, v.x, v.y, v.z, v.w);
}
__global__ void pool_cnt(const int* __restrict__ nb, float* __restrict__ cnt) {
    int i = blockIdx.x * blockDim.x + threadIdx.x;
    if (i >= TN) return;
    atomicAdd(&cnt[nb[i]], 1.f);
}
__global__ void pool_fin(float* __restrict__ emb, const float* __restrict__ cnt) {
    int i = blockIdx.x * blockDim.x + threadIdx.x;
    if (i >= BB * HH) return;
    emb[i] /= fmaxf(cnt[i >> 7], 1.f);
}

// ---------------- concat [emb | gf[cid]] ----------------
__global__ void concat_k(const float* __restrict__ emb, const float* __restrict__ gf,
                         const int* __restrict__ cid, float* __restrict__ cat) {
    int i = blockIdx.x * blockDim.x + threadIdx.x;
    if (i >= BB * (HH + FGN)) return;
    int b = i / (HH + FGN), j = i % (HH + FGN);
    cat[i] = (j < HH) ? emb[(size_t)b * HH + j]
                      : gf[(size_t)cid[b] * FGN + (j - HH)];
}

// ---------------- LayerNorm(128) + ReLU ----------------
__global__ void ln_relu_k(const float* __restrict__ X, const float* __restrict__ g,
                          const float* __restrict__ be, float* __restrict__ Y) {
    int row = blockIdx.x, t = threadIdx.x;
    float v = X[(size_t)row * HH + t];
    __shared__ float red[HH];
    red[t] = v; __syncthreads();
    for (int s = 64; s > 0; s >>= 1) { if (t < s) red[t] += red[t + s]; __syncthreads(); }
    float mean = red[0] / 128.f;
    __syncthreads();
    float dv = v - mean;
    red[t] = dv * dv; __syncthreads();
    for (int s = 64; s > 0; s >>= 1) { if (t < s) red[t] += red[t + s]; __syncthreads(); }
    float var = red[0] / 128.f;
    float y = dv * rsqrtf(var + 1e-5f) * g[t] + be[t];
    Y[(size_t)row * HH + t] = fmaxf(y, 0.f);
}

// ---------------- scatter fused batch embeddings into gx ----------------
__global__ void scatter_k(float* __restrict__ gx, const float* __restrict__ fused,
                          const int* __restrict__ cid) {
    int i = blockIdx.x * blockDim.x + threadIdx.x;
    if (i >= BB * HH) return;
    int b = i >> 7;
    gx[(size_t)cid[b] * HH + (i & 127)] = fused[i];
}

// ---------------- classifier ----------------
__global__ void classifier_k(const float* __restrict__ gx, const int* __restrict__ cid,
                             const float* __restrict__ W1, const float* __restrict__ b1,
                             const float* __restrict__ W2, const float* __restrict__ b2,
                             float* __restrict__ out) {
    int b = blockIdx.x, t = threadIdx.x;  // 64 threads
    __shared__ float row[HH];
    __shared__ float hc[HCN];
    const float* srcp = gx + (size_t)cid[b] * HH;
    row[t] = srcp[t];
    row[t + 64] = srcp[t + 64];
    __syncthreads();
    float s = b1[t];
#pragma unroll
    for (int k = 0; k < HH; k++) s += row[k] * W1[k * HCN + t];
    hc[t] = fmaxf(s, 0.f);
    __syncthreads();
    if (t < CC) {
        float s2 = b2[t];
#pragma unroll
        for (int k = 0; k < HCN; k++) s2 += hc[k] * W2[k * CC + t];
        out[b * CC + t] = s2;
    }
}

// ---------------- launch ----------------
extern "C" void kernel_launch(void* const* d_in, const int* in_sizes, int n_in,
                              void* d_out, int out_size) {
    const float* x_local    = (const float*)d_in[0];
    const float* eattr      = (const float*)d_in[1];
    const float* gfeat      = (const float*)d_in[2];
    const float* loc_in_W   = (const float*)d_in[3];
    const float* loc_in_b   = (const float*)d_in[4];
    const float* loc_W      = (const float*)d_in[5];
    const float* loc_asrc   = (const float*)d_in[6];
    const float* loc_adst   = (const float*)d_in[7];
    const float* loc_eW     = (const float*)d_in[8];
    const float* loc_ae     = (const float*)d_in[9];
    const float* loc_b      = (const float*)d_in[10];
    const float* fp_W       = (const float*)d_in[11];
    const float* fp_b       = (const float*)d_in[12];
    const float* fp_g       = (const float*)d_in[13];
    const float* fp_beta    = (const float*)d_in[14];
    const float* gp_W       = (const float*)d_in[15];
    const float* gp_b       = (const float*)d_in[16];
    const float* gp_g       = (const float*)d_in[17];
    const float* gp_beta    = (const float*)d_in[18];
    const float* glob_W     = (const float*)d_in[19];
    const float* glob_asrc  = (const float*)d_in[20];
    const float* glob_adst  = (const float*)d_in[21];
    const float* glob_b     = (const float*)d_in[22];
    const float* cls_W1     = (const float*)d_in[23];
    const float* cls_b1     = (const float*)d_in[24];
    const float* cls_W2     = (const float*)d_in[25];
    const float* cls_b2     = (const float*)d_in[26];
    const int*   eil        = (const int*)d_in[27];
    const int*   node_batch = (const int*)d_in[28];
    const int*   cid        = (const int*)d_in[29];
    const int*   gei        = (const int*)d_in[30];

    const int* lsrc = eil;
    const int* ldst = eil + ELN;
    const int* gsrc = gei;
    const int* gdst = gei + EGN;

    float *p_h, *p_z, *p_acc, *p_ssrc, *p_sdst, *p_esc, *p_den, *p_ce;
    float *p_emb, *p_cnt, *p_cat, *p_tmp, *p_fused, *p_gx, *p_gz, *p_gacc, *p_gesc, *p_gden;
    cudaGetSymbolAddress((void**)&p_h, g_h);
    cudaGetSymbolAddress((void**)&p_z, g_z);
    cudaGetSymbolAddress((void**)&p_acc, g_acc);
    cudaGetSymbolAddress((void**)&p_ssrc, g_ssrc);
    cudaGetSymbolAddress((void**)&p_sdst, g_sdst);
    cudaGetSymbolAddress((void**)&p_esc, g_esc);
    cudaGetSymbolAddress((void**)&p_den, g_den);
    cudaGetSymbolAddress((void**)&p_ce, g_ce);
    cudaGetSymbolAddress((void**)&p_emb, g_emb);
    cudaGetSymbolAddress((void**)&p_cnt, g_cnt);
    cudaGetSymbolAddress((void**)&p_cat, g_cat);
    cudaGetSymbolAddress((void**)&p_tmp, g_tmp);
    cudaGetSymbolAddress((void**)&p_fused, g_fused);
    cudaGetSymbolAddress((void**)&p_gx, g_gx);
    cudaGetSymbolAddress((void**)&p_gz, g_gz);
    cudaGetSymbolAddress((void**)&p_gacc, g_gacc);
    cudaGetSymbolAddress((void**)&p_gesc, g_gesc);
    cudaGetSymbolAddress((void**)&p_gden, g_gden);

    // ---- local encoder: input projection ----
    gemm_tile<<<CDIV(TN, 128), 256>>>(x_local, loc_in_W, loc_in_b, p_h, TN, 4);

    // ---- 2x local GATConv ----
    for (int l = 0; l < 2; l++) {
        gemm_tile<<<CDIV(TN, 128), 256>>>(p_h, loc_W + l * HH * HH, nullptr, p_z, TN, HH);
        scores_k<4, 32><<<CDIV(TN * 4, 256), 256>>>(p_z, loc_asrc + l * HH,
                                                    loc_adst + l * HH, p_ssrc, p_sdst, TN);
        ce_k<<<1, 4>>>(loc_eW + l * HH, loc_ae + l * HH, p_ce);
        cudaMemsetAsync(p_den, 0, (size_t)TN * 4 * sizeof(float));
        epass12_l<<<CDIV(ELN, 256), 256>>>(lsrc, ldst, eattr, p_ce, p_ssrc, p_sdst,
                                           p_esc, p_den, ELN);
        enorm_l<<<CDIV(ELN, 256), 256>>>(ldst, p_esc, p_den, ELN);
        accinit_k<<<CDIV(TN * HH, 256), 256>>>(p_h, loc_b + l * HH, p_acc, TN);
        epass3<4, 32><<<CDIV((long long)ELN * 32, 256), 256>>>(lsrc, ldst, p_esc, p_z, p_acc, ELN);
        elu_k<<<CDIV(TN * HH, 256), 256>>>(p_acc, p_h, TN);
    }

    // ---- contract mean pooling ----
    cudaMemsetAsync(p_emb, 0, (size_t)BB * HH * sizeof(float));
    cudaMemsetAsync(p_cnt, 0, (size_t)BB * sizeof(float));
    pool_add<<<CDIV((long long)TN * 32, 256), 256>>>(p_h, node_batch, p_emb);
    pool_cnt<<<CDIV(TN, 256), 256>>>(node_batch, p_cnt);
    pool_fin<<<CDIV(BB * HH, 256), 256>>>(p_emb, p_cnt);

    // ---- fused MLP (concat -> linear -> LN -> ReLU) ----
    concat_k<<<CDIV(BB * (HH + FGN), 256), 256>>>(p_emb, gfeat, cid, p_cat);
    gemm_tile<<<CDIV(BB, 128), 256>>>(p_cat, fp_W, fp_b, p_tmp, BB, HH + FGN);
    ln_relu_k<<<BB, HH>>>(p_tmp, fp_g, fp_beta, p_fused);

    // ---- global projection for all N nodes, then scatter fused in ----
    gemm_tile<<<CDIV(NNODE, 128), 256>>>(gfeat, gp_W, gp_b, p_gz, NNODE, FGN);
    ln_relu_k<<<NNODE, HH>>>(p_gz, gp_g, gp_beta, p_gx);
    scatter_k<<<CDIV(BB * HH, 256), 256>>>(p_gx, p_fused, cid);

    // ---- 2x global GATConv ----
    for (int l = 0; l < 2; l++) {
        gemm_tile<<<CDIV(NNODE, 128), 256>>>(p_gx, glob_W + l * HH * HH, nullptr, p_gz, NNODE, HH);
        scores_k<2, 64><<<CDIV(NNODE * 2, 256), 256>>>(p_gz, glob_asrc + l * HH,
                                                       glob_adst + l * HH, p_ssrc, p_sdst, NNODE);
        cudaMemsetAsync(p_gden, 0, (size_t)NNODE * 2 * sizeof(float));
        epass12_g<<<CDIV(EGN, 256), 256>>>(gsrc, gdst, p_ssrc, p_sdst, p_gesc, p_gden, EGN);
        enorm_g<<<CDIV(EGN, 256), 256>>>(gdst, p_gesc, p_gden, EGN);
        accinit_k<<<CDIV(NNODE * HH, 256), 256>>>(p_gx, glob_b + l * HH, p_gacc, NNODE);
        epass3<2, 64><<<CDIV((long long)EGN * 32, 256), 256>>>(gsrc, gdst, p_gesc, p_gz, p_gacc, EGN);
        elu_k<<<CDIV(NNODE * HH, 256), 256>>>(p_gacc, p_gx, NNODE);
    }

    // ---- classifier ----
    classifier_k<<<BB, 64>>>(p_gx, cid, cls_W1, cls_b1, cls_W2, cls_b2, (float*)d_out);
}

// round 3
// speedup vs baseline: 1.8578x; 1.1562x over previous
#include <cuda_runtime.h>
#include <math.h>

// ---------------- problem constants ----------------
#define TN    131072     // local tx nodes
#define ELN   524288     // local edges
#define NNODE 50000      // global contract nodes
#define EGN   400000     // global edges
#define BB    8192       // batch of contracts
#define HH    128        // hidden dim
#define FGN   7          // global feat dim
#define HCN   64         // classifier hidden
#define CC    2          // classes

#define CDIV(a,b) (((a)+(b)-1)/(b))

// ---------------- scratch (device globals) ----------------
__device__ float g_h   [TN*HH];
__device__ float g_z   [TN*HH];
__device__ float g_acc [TN*HH];
__device__ float g_ssrc[TN*4];
__device__ float g_sdst[TN*4];
__device__ float g_esc [ELN*4];
__device__ float g_den [TN*4];
__device__ float g_emb [BB*HH];
__device__ float g_cnt [BB];
__device__ float g_cat [BB*(HH+FGN)];
__device__ float g_tmp [BB*HH];
__device__ float g_fused[BB*HH];
__device__ float g_gx  [NNODE*HH];
__device__ float g_gz  [NNODE*HH];
__device__ float g_gacc[NNODE*HH];
__device__ float g_gesc[EGN*2];
__device__ float g_gden[NNODE*2];

// ---------------- vector reductions (sm_90+) ----------------
__device__ __forceinline__ void red_add_v4(float* a, float x, float y, float z, float w) {
    asm volatile("red.global.add.v4.f32 [%0], {%1,%2,%3,%4};"
                 :: "l"(a), "f"(x), "f"(y), "f"(z), "f"(w) : "memory");
}
__device__ __forceinline__ void red_add_v2(float* a, float x, float y) {
    asm volatile("red.global.add.v2.f32 [%0], {%1,%2};"
                 :: "l"(a), "f"(x), "f"(y) : "memory");
}
__device__ __forceinline__ unsigned f2tf32(float f) {
    unsigned r;
    asm("cvt.rna.tf32.f32 %0, %1;" : "=r"(r) : "f"(f));
    return r;
}

// ---------------- tf32 MMA GEMM: C[M,128] = A[M,K] @ W[K,128] (+bias) ----------------
// 128x128 block tile, 8 warps (4x2), warp tile 32x64, K-tile 32, mma m16n8k8.
#define A_PAD 36
#define W_PAD 136
__global__ __launch_bounds__(256, 2)
void gemm_mma(const float* __restrict__ A, const float* __restrict__ W,
              const float* __restrict__ bias, float* __restrict__ C,
              int M, int K) {
    __shared__ unsigned As[128 * A_PAD];  // [m][k], k-pad 36
    __shared__ unsigned Ws[32 * W_PAD];   // [k][n], n-pad 136
    const int tid  = threadIdx.x;
    const int warp = tid >> 5, lane = tid & 31;
    const int bm   = blockIdx.x * 128;
    const int wm   = (warp >> 1) * 32;    // warp row offset
    const int wn   = (warp & 1) * 64;     // warp col offset
    const int g    = lane >> 2;           // groupID
    const int ct   = lane & 3;            // thread-in-group

    float c[2][8][4];
#pragma unroll
    for (int mt = 0; mt < 2; mt++)
#pragma unroll
        for (int nt = 0; nt < 8; nt++)
#pragma unroll
            for (int r = 0; r < 4; r++) c[mt][nt][r] = 0.f;

    for (int k0 = 0; k0 < K; k0 += 32) {
        // load A tile 128x32 (tf32-converted)
#pragma unroll
        for (int i = tid; i < 128 * 32; i += 256) {
            int m = i >> 5, k = i & 31;
            int gr = bm + m, gk = k0 + k;
            float v = (gr < M && gk < K) ? A[(size_t)gr * K + gk] : 0.f;
            As[m * A_PAD + k] = f2tf32(v);
        }
        // load W tile 32x128
#pragma unroll
        for (int i = tid; i < 32 * 128; i += 256) {
            int k = i >> 7, n = i & 127;
            int gk = k0 + k;
            float v = (gk < K) ? W[gk * 128 + n] : 0.f;
            Ws[k * W_PAD + n] = f2tf32(v);
        }
        __syncthreads();

#pragma unroll
        for (int ks = 0; ks < 32; ks += 8) {
            unsigned b[8][2];
#pragma unroll
            for (int nt = 0; nt < 8; nt++) {
                int n = wn + nt * 8 + g;
                b[nt][0] = Ws[(ks + ct) * W_PAD + n];
                b[nt][1] = Ws[(ks + ct + 4) * W_PAD + n];
            }
#pragma unroll
            for (int mt = 0; mt < 2; mt++) {
                int r0 = wm + mt * 16 + g;
                unsigned a0 = As[r0 * A_PAD + ks + ct];
                unsigned a1 = As[(r0 + 8) * A_PAD + ks + ct];
                unsigned a2 = As[r0 * A_PAD + ks + ct + 4];
                unsigned a3 = As[(r0 + 8) * A_PAD + ks + ct + 4];
#pragma unroll
                for (int nt = 0; nt < 8; nt++) {
                    asm volatile(
                        "mma.sync.aligned.m16n8k8.row.col.f32.tf32.tf32.f32 "
                        "{%0,%1,%2,%3}, {%4,%5,%6,%7}, {%8,%9}, {%0,%1,%2,%3};"
                        : "+f"(c[mt][nt][0]), "+f"(c[mt][nt][1]),
                          "+f"(c[mt][nt][2]), "+f"(c[mt][nt][3])
                        : "r"(a0), "r"(a1), "r"(a2), "r"(a3),
                          "r"(b[nt][0]), "r"(b[nt][1]));
                }
            }
        }
        __syncthreads();
    }

    // epilogue: c0/c1 = (row g, cols 2ct,2ct+1); c2/c3 = row g+8
#pragma unroll
    for (int mt = 0; mt < 2; mt++) {
        int row0 = bm + wm + mt * 16 + g;
        int row1 = row0 + 8;
#pragma unroll
        for (int nt = 0; nt < 8; nt++) {
            int col = wn + nt * 8 + 2 * ct;
            float b0 = bias ? bias[col] : 0.f;
            float b1 = bias ? bias[col + 1] : 0.f;
            if (row0 < M)
                *(float2*)(C + (size_t)row0 * 128 + col) =
                    make_float2(c[mt][nt][0] + b0, c[mt][nt][1] + b1);
            if (row1 < M)
                *(float2*)(C + (size_t)row1 * 128 + col) =
                    make_float2(c[mt][nt][2] + b0, c[mt][nt][3] + b1);
        }
    }
}

// ---------------- SIMT GEMM for tiny-K projections ----------------
__global__ __launch_bounds__(256, 2)
void gemm_tile(const float* __restrict__ A, const float* __restrict__ W,
               const float* __restrict__ bias, float* __restrict__ C,
               int M, int K) {
    __shared__ float As[16 * 132];
    __shared__ float Ws[16 * 132];
    const int bm  = blockIdx.x * 128;
    const int tid = threadIdx.x;
    const int tr  = (tid >> 4) * 8;
    const int tc  = (tid & 15) * 8;
    float acc[8][8];
#pragma unroll
    for (int x = 0; x < 8; x++)
#pragma unroll
        for (int y = 0; y < 8; y++) acc[x][y] = 0.f;

    for (int k0 = 0; k0 < K; k0 += 16) {
        for (int i = tid; i < 128 * 16; i += 256) {
            int m = i >> 4, kk = i & 15;
            int gr = bm + m, gk = k0 + kk;
            As[kk * 132 + m] = (gr < M && gk < K) ? A[(size_t)gr * K + gk] : 0.f;
        }
        for (int i = tid; i < 16 * 128; i += 256) {
            int kk = i >> 7, n = i & 127;
            int gk = k0 + kk;
            Ws[kk * 132 + n] = (gk < K) ? W[gk * 128 + n] : 0.f;
        }
        __syncthreads();
#pragma unroll
        for (int kk = 0; kk < 16; kk++) {
            float a[8], w[8];
#pragma unroll
            for (int x = 0; x < 8; x++) a[x] = As[kk * 132 + tr + x];
#pragma unroll
            for (int y = 0; y < 8; y++) w[y] = Ws[kk * 132 + tc + y];
#pragma unroll
            for (int x = 0; x < 8; x++)
#pragma unroll
                for (int y = 0; y < 8; y++) acc[x][y] += a[x] * w[y];
        }
        __syncthreads();
    }
#pragma unroll
    for (int x = 0; x < 8; x++) {
        int gr = bm + tr + x;
        if (gr < M) {
#pragma unroll
            for (int y = 0; y < 8; y++) {
                float v = acc[x][y];
                if (bias) v += bias[tc + y];
                C[(size_t)gr * 128 + tc + y] = v;
            }
        }
    }
}

// ---------------- per-node attention scores ----------------
template <int NH, int HD>
__global__ void scores_k(const float* __restrict__ z, const float* __restrict__ as_,
                         const float* __restrict__ ad_, float* __restrict__ ssrc,
                         float* __restrict__ sdst, int n) {
    int i = blockIdx.x * blockDim.x + threadIdx.x;
    if (i >= n * NH) return;
    int node = i / NH, h = i % NH;
    const float* zp = z + (size_t)node * HH + h * HD;
    const float* ap = as_ + h * HD;
    const float* dp = ad_ + h * HD;
    float s = 0.f, t = 0.f;
#pragma unroll
    for (int d = 0; d < HD; d++) { float zv = zp[d]; s += zv * ap[d]; t += zv * dp[d]; }
    ssrc[i] = s; sdst[i] = t;
}

// ---------------- merged edge pass: score+leaky+exp+denominator (local) ----------------
// ce (per-head edge-attr constant) computed per block in smem.
__global__ void epass12_l(const int* __restrict__ src, const int* __restrict__ dst,
                          const float* __restrict__ eattr,
                          const float* __restrict__ eW, const float* __restrict__ ae,
                          const float* __restrict__ ssrc, const float* __restrict__ sdst,
                          float* __restrict__ ex, float* __restrict__ den, int E) {
    __shared__ float ce[4];
    if (threadIdx.x < 4) {
        int h = threadIdx.x;
        float s = 0.f;
#pragma unroll
        for (int d = 0; d < 32; d++) s += eW[h * 32 + d] * ae[h * 32 + d];
        ce[h] = s;
    }
    __syncthreads();
    int e = blockIdx.x * blockDim.x + threadIdx.x;
    if (e >= E) return;
    int s = src[e], d = dst[e];
    float4 ss = *(const float4*)(ssrc + (size_t)s * 4);
    float4 sd = *(const float4*)(sdst + (size_t)d * 4);
    float ea = eattr[e];
    float c0 = ss.x + sd.x + ea * ce[0];
    float c1 = ss.y + sd.y + ea * ce[1];
    float c2 = ss.z + sd.z + ea * ce[2];
    float c3 = ss.w + sd.w + ea * ce[3];
    c0 = c0 > 0.f ? c0 : 0.2f * c0;  c1 = c1 > 0.f ? c1 : 0.2f * c1;
    c2 = c2 > 0.f ? c2 : 0.2f * c2;  c3 = c3 > 0.f ? c3 : 0.2f * c3;
    float e0 = expf(c0), e1 = expf(c1), e2 = expf(c2), e3 = expf(c3);
    *(float4*)(ex + (size_t)e * 4) = make_float4(e0, e1, e2, e3);
    red_add_v4(den + (size_t)d * 4, e0, e1, e2, e3);
}

__global__ void epass12_g(const int* __restrict__ src, const int* __restrict__ dst,
                          const float* __restrict__ ssrc, const float* __restrict__ sdst,
                          float* __restrict__ ex, float* __restrict__ den, int E) {
    int e = blockIdx.x * blockDim.x + threadIdx.x;
    if (e >= E) return;
    int s = src[e], d = dst[e];
    float2 ss = *(const float2*)(ssrc + (size_t)s * 2);
    float2 sd = *(const float2*)(sdst + (size_t)d * 2);
    float c0 = ss.x + sd.x, c1 = ss.y + sd.y;
    c0 = c0 > 0.f ? c0 : 0.2f * c0;  c1 = c1 > 0.f ? c1 : 0.2f * c1;
    float e0 = expf(c0), e1 = expf(c1);
    *(float2*)(ex + (size_t)e * 2) = make_float2(e0, e1);
    red_add_v2(den + (size_t)d * 2, e0, e1);
}

// ---------------- weighted scatter with in-flight normalization ----------------
// one thread per (edge, 4 channels); warp = one edge.
template <int NH, int HD>
__global__ void epass3(const int* __restrict__ src, const int* __restrict__ dst,
                       const float* __restrict__ ex, const float* __restrict__ den,
                       const float* __restrict__ z, float* __restrict__ acc, int E) {
    long long i = (long long)blockIdx.x * blockDim.x + threadIdx.x;
    if (i >= (long long)E * 32) return;
    int e = (int)(i >> 5), q = (int)(i & 31);
    int c = q * 4;
    int h = c / HD;
    int s = src[e], d = dst[e];
    float a = ex[(size_t)e * NH + h] / fmaxf(den[(size_t)d * NH + h], 1e-16f);
    float4 zv = *(const float4*)(z + (size_t)s * HH + c);
    red_add_v4(acc + (size_t)d * HH + c, a * zv.x, a * zv.y, a * zv.z, a * zv.w);
}

// ---------------- acc init (residual + bias), ELU finish ----------------
__global__ void accinit_k(const float* __restrict__ h, const float* __restrict__ b,
                          float* __restrict__ acc, int n) {
    int i = blockIdx.x * blockDim.x + threadIdx.x;
    if (i >= n * HH) return;
    acc[i] = h[i] + b[i & 127];
}
__global__ void elu_k(const float* __restrict__ acc, float* __restrict__ h, int n) {
    int i = blockIdx.x * blockDim.x + threadIdx.x;
    if (i >= n * HH) return;
    float x = acc[i];
    h[i] = x > 0.f ? x : expf(x) - 1.f;
}

// ---------------- mean pooling ----------------
__global__ void pool_add(const float* __restrict__ h, const int* __restrict__ nb,
                         float* __restrict__ emb) {
    long long i = (long long)blockIdx.x * blockDim.x + threadIdx.x;
    if (i >= (long long)TN * 32) return;
    int node = (int)(i >> 5), c = (int)(i & 31) * 4;
    int b = nb[node];
    float4 v = *(const float4*)(h + (size_t)node * HH + c);
    red_add_v4(emb + (size_t)b * HH + c, v.x, v.y, v.z, v.w);
}
__global__ void pool_cnt(const int* __restrict__ nb, float* __restrict__ cnt) {
    int i = blockIdx.x * blockDim.x + threadIdx.x;
    if (i >= TN) return;
    atomicAdd(&cnt[nb[i]], 1.f);
}
__global__ void pool_fin(float* __restrict__ emb, const float* __restrict__ cnt) {
    int i = blockIdx.x * blockDim.x + threadIdx.x;
    if (i >= BB * HH) return;
    emb[i] /= fmaxf(cnt[i >> 7], 1.f);
}

// ---------------- concat [emb | gf[cid]] ----------------
__global__ void concat_k(const float* __restrict__ emb, const float* __restrict__ gf,
                         const int* __restrict__ cid, float* __restrict__ cat) {
    int i = blockIdx.x * blockDim.x + threadIdx.x;
    if (i >= BB * (HH + FGN)) return;
    int b = i / (HH + FGN), j = i % (HH + FGN);
    cat[i] = (j < HH) ? emb[(size_t)b * HH + j]
                      : gf[(size_t)cid[b] * FGN + (j - HH)];
}

// ---------------- LayerNorm(128) + ReLU ----------------
__global__ void ln_relu_k(const float* __restrict__ X, const float* __restrict__ g,
                          const float* __restrict__ be, float* __restrict__ Y) {
    int row = blockIdx.x, t = threadIdx.x;
    float v = X[(size_t)row * HH + t];
    __shared__ float red[HH];
    red[t] = v; __syncthreads();
    for (int s = 64; s > 0; s >>= 1) { if (t < s) red[t] += red[t + s]; __syncthreads(); }
    float mean = red[0] / 128.f;
    __syncthreads();
    float dv = v - mean;
    red[t] = dv * dv; __syncthreads();
    for (int s = 64; s > 0; s >>= 1) { if (t < s) red[t] += red[t + s]; __syncthreads(); }
    float var = red[0] / 128.f;
    float y = dv * rsqrtf(var + 1e-5f) * g[t] + be[t];
    Y[(size_t)row * HH + t] = fmaxf(y, 0.f);
}

// ---------------- scatter fused batch embeddings into gx ----------------
__global__ void scatter_k(float* __restrict__ gx, const float* __restrict__ fused,
                          const int* __restrict__ cid) {
    int i = blockIdx.x * blockDim.x + threadIdx.x;
    if (i >= BB * HH) return;
    int b = i >> 7;
    gx[(size_t)cid[b] * HH + (i & 127)] = fused[i];
}

// ---------------- classifier ----------------
__global__ void classifier_k(const float* __restrict__ gx, const int* __restrict__ cid,
                             const float* __restrict__ W1, const float* __restrict__ b1,
                             const float* __restrict__ W2, const float* __restrict__ b2,
                             float* __restrict__ out) {
    int b = blockIdx.x, t = threadIdx.x;  // 64 threads
    __shared__ float row[HH];
    __shared__ float hc[HCN];
    const float* srcp = gx + (size_t)cid[b] * HH;
    row[t] = srcp[t];
    row[t + 64] = srcp[t + 64];
    __syncthreads();
    float s = b1[t];
#pragma unroll
    for (int k = 0; k < HH; k++) s += row[k] * W1[k * HCN + t];
    hc[t] = fmaxf(s, 0.f);
    __syncthreads();
    if (t < CC) {
        float s2 = b2[t];
#pragma unroll
        for (int k = 0; k < HCN; k++) s2 += hc[k] * W2[k * CC + t];
        out[b * CC + t] = s2;
    }
}

// ---------------- launch ----------------
extern "C" void kernel_launch(void* const* d_in, const int* in_sizes, int n_in,
                              void* d_out, int out_size) {
    const float* x_local    = (const float*)d_in[0];
    const float* eattr      = (const float*)d_in[1];
    const float* gfeat      = (const float*)d_in[2];
    const float* loc_in_W   = (const float*)d_in[3];
    const float* loc_in_b   = (const float*)d_in[4];
    const float* loc_W      = (const float*)d_in[5];
    const float* loc_asrc   = (const float*)d_in[6];
    const float* loc_adst   = (const float*)d_in[7];
    const float* loc_eW     = (const float*)d_in[8];
    const float* loc_ae     = (const float*)d_in[9];
    const float* loc_b      = (const float*)d_in[10];
    const float* fp_W       = (const float*)d_in[11];
    const float* fp_b       = (const float*)d_in[12];
    const float* fp_g       = (const float*)d_in[13];
    const float* fp_beta    = (const float*)d_in[14];
    const float* gp_W       = (const float*)d_in[15];
    const float* gp_b       = (const float*)d_in[16];
    const float* gp_g       = (const float*)d_in[17];
    const float* gp_beta    = (const float*)d_in[18];
    const float* glob_W     = (const float*)d_in[19];
    const float* glob_asrc  = (const float*)d_in[20];
    const float* glob_adst  = (const float*)d_in[21];
    const float* glob_b     = (const float*)d_in[22];
    const float* cls_W1     = (const float*)d_in[23];
    const float* cls_b1     = (const float*)d_in[24];
    const float* cls_W2     = (const float*)d_in[25];
    const float* cls_b2     = (const float*)d_in[26];
    const int*   eil        = (const int*)d_in[27];
    const int*   node_batch = (const int*)d_in[28];
    const int*   cid        = (const int*)d_in[29];
    const int*   gei        = (const int*)d_in[30];

    const int* lsrc = eil;
    const int* ldst = eil + ELN;
    const int* gsrc = gei;
    const int* gdst = gei + EGN;

    float *p_h, *p_z, *p_acc, *p_ssrc, *p_sdst, *p_esc, *p_den;
    float *p_emb, *p_cnt, *p_cat, *p_tmp, *p_fused, *p_gx, *p_gz, *p_gacc, *p_gesc, *p_gden;
    cudaGetSymbolAddress((void**)&p_h, g_h);
    cudaGetSymbolAddress((void**)&p_z, g_z);
    cudaGetSymbolAddress((void**)&p_acc, g_acc);
    cudaGetSymbolAddress((void**)&p_ssrc, g_ssrc);
    cudaGetSymbolAddress((void**)&p_sdst, g_sdst);
    cudaGetSymbolAddress((void**)&p_esc, g_esc);
    cudaGetSymbolAddress((void**)&p_den, g_den);
    cudaGetSymbolAddress((void**)&p_emb, g_emb);
    cudaGetSymbolAddress((void**)&p_cnt, g_cnt);
    cudaGetSymbolAddress((void**)&p_cat, g_cat);
    cudaGetSymbolAddress((void**)&p_tmp, g_tmp);
    cudaGetSymbolAddress((void**)&p_fused, g_fused);
    cudaGetSymbolAddress((void**)&p_gx, g_gx);
    cudaGetSymbolAddress((void**)&p_gz, g_gz);
    cudaGetSymbolAddress((void**)&p_gacc, g_gacc);
    cudaGetSymbolAddress((void**)&p_gesc, g_gesc);
    cudaGetSymbolAddress((void**)&p_gden, g_gden);

    // ---- local encoder: input projection (K=4, SIMT) ----
    gemm_tile<<<CDIV(TN, 128), 256>>>(x_local, loc_in_W, loc_in_b, p_h, TN, 4);

    // ---- 2x local GATConv ----
    for (int l = 0; l < 2; l++) {
        gemm_mma<<<CDIV(TN, 128), 256>>>(p_h, loc_W + l * HH * HH, nullptr, p_z, TN, HH);
        scores_k<4, 32><<<CDIV(TN * 4, 256), 256>>>(p_z, loc_asrc + l * HH,
                                                    loc_adst + l * HH, p_ssrc, p_sdst, TN);
        cudaMemsetAsync(p_den, 0, (size_t)TN * 4 * sizeof(float));
        epass12_l<<<CDIV(ELN, 256), 256>>>(lsrc, ldst, eattr, loc_eW + l * HH,
                                           loc_ae + l * HH, p_ssrc, p_sdst, p_esc, p_den, ELN);
        accinit_k<<<CDIV(TN * HH, 256), 256>>>(p_h, loc_b + l * HH, p_acc, TN);
        epass3<4, 32><<<CDIV((long long)ELN * 32, 256), 256>>>(lsrc, ldst, p_esc, p_den,
                                                               p_z, p_acc, ELN);
        elu_k<<<CDIV(TN * HH, 256), 256>>>(p_acc, p_h, TN);
    }

    // ---- contract mean pooling ----
    cudaMemsetAsync(p_emb, 0, (size_t)BB * HH * sizeof(float));
    cudaMemsetAsync(p_cnt, 0, (size_t)BB * sizeof(float));
    pool_add<<<CDIV((long long)TN * 32, 256), 256>>>(p_h, node_batch, p_emb);
    pool_cnt<<<CDIV(TN, 256), 256>>>(node_batch, p_cnt);
    pool_fin<<<CDIV(BB * HH, 256), 256>>>(p_emb, p_cnt);

    // ---- fused MLP (concat -> linear(K=135, MMA) -> LN -> ReLU) ----
    concat_k<<<CDIV(BB * (HH + FGN), 256), 256>>>(p_emb, gfeat, cid, p_cat);
    gemm_mma<<<CDIV(BB, 128), 256>>>(p_cat, fp_W, fp_b, p_tmp, BB, HH + FGN);
    ln_relu_k<<<BB, HH>>>(p_tmp, fp_g, fp_beta, p_fused);

    // ---- global projection for all N nodes (K=7, SIMT), scatter fused in ----
    gemm_tile<<<CDIV(NNODE, 128), 256>>>(gfeat, gp_W, gp_b, p_gz, NNODE, FGN);
    ln_relu_k<<<NNODE, HH>>>(p_gz, gp_g, gp_beta, p_gx);
    scatter_k<<<CDIV(BB * HH, 256), 256>>>(p_gx, p_fused, cid);

    // ---- 2x global GATConv ----
    for (int l = 0; l < 2; l++) {
        gemm_mma<<<CDIV(NNODE, 128), 256>>>(p_gx, glob_W + l * HH * HH, nullptr, p_gz, NNODE, HH);
        scores_k<2, 64><<<CDIV(NNODE * 2, 256), 256>>>(p_gz, glob_asrc + l * HH,
                                                       glob_adst + l * HH, p_ssrc, p_sdst, NNODE);
        cudaMemsetAsync(p_gden, 0, (size_t)NNODE * 2 * sizeof(float));
        epass12_g<<<CDIV(EGN, 256), 256>>>(gsrc, gdst, p_ssrc, p_sdst, p_gesc, p_gden, EGN);
        accinit_k<<<CDIV(NNODE * HH, 256), 256>>>(p_gx, glob_b + l * HH, p_gacc, NNODE);
        epass3<2, 64><<<CDIV((long long)EGN * 32, 256), 256>>>(gsrc, gdst, p_gesc, p_gden,
                                                               p_gz, p_gacc, EGN);
        elu_k<<<CDIV(NNODE * HH, 256), 256>>>(p_gacc, p_gx, NNODE);
    }

    // ---- classifier ----
    classifier_k<<<BB, 64>>>(p_gx, cid, cls_W1, cls_b1, cls_W2, cls_b2, (float*)d_out);
}

// round 4
// speedup vs baseline: 2.5394x; 1.3669x over previous
#include <cuda_runtime.h>
#include <math.h>

// ---------------- problem constants ----------------
#define TN    131072     // local tx nodes
#define ELN   524288     // local edges
#define NNODE 50000      // global contract nodes
#define EGN   400000     // global edges
#define BB    8192       // batch of contracts
#define HH    128        // hidden dim
#define FGN   7          // global feat dim
#define HCN   64         // classifier hidden
#define CC    2          // classes

#define CDIV(a,b) (((a)+(b)-1)/(b))

// ---------------- scratch (device globals) ----------------
__device__ float g_h   [TN*HH];
__device__ float g_z   [TN*HH];
__device__ float g_ssrc[TN*4];
__device__ float g_sdst[TN*4];
__device__ float g_esc [ELN*4];
__device__ float g_den [TN*4];
__device__ float g_emb [BB*HH];
__device__ float g_cat [BB*(HH+FGN)];
__device__ float g_tmp [BB*HH];
__device__ float g_fused[BB*HH];
__device__ float g_gx  [NNODE*HH];
__device__ float g_gz  [NNODE*HH];
__device__ float g_gesc[EGN*2];
__device__ float g_gden[NNODE*2];
// CSR scratch
__device__ int g_deg   [TN];
__device__ int g_rowptr[TN+1];
__device__ int g_fill  [TN];
__device__ int g_perm  [ELN];
__device__ int g_bsum  [256];
__device__ int g_gdeg   [NNODE];
__device__ int g_growptr[NNODE+1];
__device__ int g_gfill  [NNODE];
__device__ int g_gperm  [EGN];
__device__ int g_gbsum  [256];

// ---------------- helpers ----------------
__device__ __forceinline__ void red_add_v4(float* a, float x, float y, float z, float w) {
    asm volatile("red.global.add.v4.f32 [%0], {%1,%2,%3,%4};"
                 :: "l"(a), "f"(x), "f"(y), "f"(z), "f"(w) : "memory");
}
__device__ __forceinline__ void red_add_v2(float* a, float x, float y) {
    asm volatile("red.global.add.v2.f32 [%0], {%1,%2};"
                 :: "l"(a), "f"(x), "f"(y) : "memory");
}
__device__ __forceinline__ unsigned f2tf32(float f) {
    unsigned r;
    asm("cvt.rna.tf32.f32 %0, %1;" : "=r"(r) : "f"(f));
    return r;
}

// ================= CSR construction =================
__global__ void hist_k(const int* __restrict__ dst, int* __restrict__ deg, int E) {
    int e = blockIdx.x * blockDim.x + threadIdx.x;
    if (e < E) atomicAdd(&deg[dst[e]], 1);
}
// block sums over 1024-element chunks
__global__ void scan1_k(const int* __restrict__ deg, int* __restrict__ bsum, int n) {
    __shared__ int s[256];
    int base = blockIdx.x * 1024, t = threadIdx.x;
    int sum = 0;
#pragma unroll
    for (int i = 0; i < 4; i++) {
        int idx = base + t * 4 + i;
        if (idx < n) sum += deg[idx];
    }
    s[t] = sum; __syncthreads();
    for (int o = 128; o > 0; o >>= 1) { if (t < o) s[t] += s[t + o]; __syncthreads(); }
    if (t == 0) bsum[blockIdx.x] = s[0];
}
__global__ void scan2_k(int* __restrict__ bsum, int nb, int* __restrict__ rowptr,
                        int n, int E) {
    if (threadIdx.x == 0) {
        int acc = 0;
        for (int i = 0; i < nb; i++) { int v = bsum[i]; bsum[i] = acc; acc += v; }
        rowptr[n] = E;
    }
}
__global__ void scan3_k(const int* __restrict__ deg, const int* __restrict__ bsum,
                        int* __restrict__ rowptr, int* __restrict__ fill, int n) {
    __shared__ int s[256];
    int base = blockIdx.x * 1024, t = threadIdx.x;
    int v[4]; int sum = 0;
#pragma unroll
    for (int i = 0; i < 4; i++) {
        int idx = base + t * 4 + i;
        v[i] = (idx < n) ? deg[idx] : 0;
        sum += v[i];
    }
    s[t] = sum; __syncthreads();
    for (int o = 1; o < 256; o <<= 1) {
        int x = (t >= o) ? s[t - o] : 0;
        __syncthreads();
        s[t] += x;
        __syncthreads();
    }
    int excl = ((t == 0) ? 0 : s[t - 1]) + bsum[blockIdx.x];
#pragma unroll
    for (int i = 0; i < 4; i++) {
        int idx = base + t * 4 + i;
        if (idx < n) { rowptr[idx] = excl; fill[idx] = excl; }
        excl += v[i];
    }
}
__global__ void scatedge_k(const int* __restrict__ dst, int* __restrict__ fill,
                           int* __restrict__ perm, int E) {
    int e = blockIdx.x * blockDim.x + threadIdx.x;
    if (e < E) { int p = atomicAdd(&fill[dst[e]], 1); perm[p] = e; }
}

// ================= tf32 MMA GEMM =================
#define A_PAD 36
#define W_PAD 136
__global__ __launch_bounds__(256, 2)
void gemm_mma(const float* __restrict__ A, const float* __restrict__ W,
              const float* __restrict__ bias, float* __restrict__ C,
              int M, int K) {
    __shared__ unsigned As[128 * A_PAD];
    __shared__ unsigned Ws[32 * W_PAD];
    const int tid  = threadIdx.x;
    const int warp = tid >> 5, lane = tid & 31;
    const int bm   = blockIdx.x * 128;
    const int wm   = (warp >> 1) * 32;
    const int wn   = (warp & 1) * 64;
    const int g    = lane >> 2;
    const int ct   = lane & 3;

    float c[2][8][4];
#pragma unroll
    for (int mt = 0; mt < 2; mt++)
#pragma unroll
        for (int nt = 0; nt < 8; nt++)
#pragma unroll
            for (int r = 0; r < 4; r++) c[mt][nt][r] = 0.f;

    for (int k0 = 0; k0 < K; k0 += 32) {
#pragma unroll
        for (int i = tid; i < 128 * 32; i += 256) {
            int m = i >> 5, k = i & 31;
            int gr = bm + m, gk = k0 + k;
            float v = (gr < M && gk < K) ? A[(size_t)gr * K + gk] : 0.f;
            As[m * A_PAD + k] = f2tf32(v);
        }
#pragma unroll
        for (int i = tid; i < 32 * 128; i += 256) {
            int k = i >> 7, n = i & 127;
            int gk = k0 + k;
            float v = (gk < K) ? W[gk * 128 + n] : 0.f;
            Ws[k * W_PAD + n] = f2tf32(v);
        }
        __syncthreads();
#pragma unroll
        for (int ks = 0; ks < 32; ks += 8) {
            unsigned b[8][2];
#pragma unroll
            for (int nt = 0; nt < 8; nt++) {
                int n = wn + nt * 8 + g;
                b[nt][0] = Ws[(ks + ct) * W_PAD + n];
                b[nt][1] = Ws[(ks + ct + 4) * W_PAD + n];
            }
#pragma unroll
            for (int mt = 0; mt < 2; mt++) {
                int r0 = wm + mt * 16 + g;
                unsigned a0 = As[r0 * A_PAD + ks + ct];
                unsigned a1 = As[(r0 + 8) * A_PAD + ks + ct];
                unsigned a2 = As[r0 * A_PAD + ks + ct + 4];
                unsigned a3 = As[(r0 + 8) * A_PAD + ks + ct + 4];
#pragma unroll
                for (int nt = 0; nt < 8; nt++) {
                    asm volatile(
                        "mma.sync.aligned.m16n8k8.row.col.f32.tf32.tf32.f32 "
                        "{%0,%1,%2,%3}, {%4,%5,%6,%7}, {%8,%9}, {%0,%1,%2,%3};"
                        : "+f"(c[mt][nt][0]), "+f"(c[mt][nt][1]),
                          "+f"(c[mt][nt][2]), "+f"(c[mt][nt][3])
                        : "r"(a0), "r"(a1), "r"(a2), "r"(a3),
                          "r"(b[nt][0]), "r"(b[nt][1]));
                }
            }
        }
        __syncthreads();
    }
#pragma unroll
    for (int mt = 0; mt < 2; mt++) {
        int row0 = bm + wm + mt * 16 + g;
        int row1 = row0 + 8;
#pragma unroll
        for (int nt = 0; nt < 8; nt++) {
            int col = wn + nt * 8 + 2 * ct;
            float b0 = bias ? bias[col] : 0.f;
            float b1 = bias ? bias[col + 1] : 0.f;
            if (row0 < M)
                *(float2*)(C + (size_t)row0 * 128 + col) =
                    make_float2(c[mt][nt][0] + b0, c[mt][nt][1] + b1);
            if (row1 < M)
                *(float2*)(C + (size_t)row1 * 128 + col) =
                    make_float2(c[mt][nt][2] + b0, c[mt][nt][3] + b1);
        }
    }
}

// ---------------- SIMT GEMM for tiny-K projections ----------------
__global__ __launch_bounds__(256, 2)
void gemm_tile(const float* __restrict__ A, const float* __restrict__ W,
               const float* __restrict__ bias, float* __restrict__ C,
               int M, int K) {
    __shared__ float As[16 * 132];
    __shared__ float Ws[16 * 132];
    const int bm  = blockIdx.x * 128;
    const int tid = threadIdx.x;
    const int tr  = (tid >> 4) * 8;
    const int tc  = (tid & 15) * 8;
    float acc[8][8];
#pragma unroll
    for (int x = 0; x < 8; x++)
#pragma unroll
        for (int y = 0; y < 8; y++) acc[x][y] = 0.f;

    for (int k0 = 0; k0 < K; k0 += 16) {
        for (int i = tid; i < 128 * 16; i += 256) {
            int m = i >> 4, kk = i & 15;
            int gr = bm + m, gk = k0 + kk;
            As[kk * 132 + m] = (gr < M && gk < K) ? A[(size_t)gr * K + gk] : 0.f;
        }
        for (int i = tid; i < 16 * 128; i += 256) {
            int kk = i >> 7, n = i & 127;
            int gk = k0 + kk;
            Ws[kk * 132 + n] = (gk < K) ? W[gk * 128 + n] : 0.f;
        }
        __syncthreads();
#pragma unroll
        for (int kk = 0; kk < 16; kk++) {
            float a[8], w[8];
#pragma unroll
            for (int x = 0; x < 8; x++) a[x] = As[kk * 132 + tr + x];
#pragma unroll
            for (int y = 0; y < 8; y++) w[y] = Ws[kk * 132 + tc + y];
#pragma unroll
            for (int x = 0; x < 8; x++)
#pragma unroll
                for (int y = 0; y < 8; y++) acc[x][y] += a[x] * w[y];
        }
        __syncthreads();
    }
#pragma unroll
    for (int x = 0; x < 8; x++) {
        int gr = bm + tr + x;
        if (gr < M) {
#pragma unroll
            for (int y = 0; y < 8; y++) {
                float v = acc[x][y];
                if (bias) v += bias[tc + y];
                C[(size_t)gr * 128 + tc + y] = v;
            }
        }
    }
}

// ---------------- per-node attention scores ----------------
template <int NH, int HD>
__global__ void scores_k(const float* __restrict__ z, const float* __restrict__ as_,
                         const float* __restrict__ ad_, float* __restrict__ ssrc,
                         float* __restrict__ sdst, int n) {
    int i = blockIdx.x * blockDim.x + threadIdx.x;
    if (i >= n * NH) return;
    int node = i / NH, h = i % NH;
    const float* zp = z + (size_t)node * HH + h * HD;
    const float* ap = as_ + h * HD;
    const float* dp = ad_ + h * HD;
    float s = 0.f, t = 0.f;
#pragma unroll
    for (int d = 0; d < HD; d++) { float zv = zp[d]; s += zv * ap[d]; t += zv * dp[d]; }
    ssrc[i] = s; sdst[i] = t;
}

// ---------------- merged edge pass: score+leaky+exp+denominator ----------------
__global__ void epass12_l(const int* __restrict__ src, const int* __restrict__ dst,
                          const float* __restrict__ eattr,
                          const float* __restrict__ eW, const float* __restrict__ ae,
                          const float* __restrict__ ssrc, const float* __restrict__ sdst,
                          float* __restrict__ ex, float* __restrict__ den, int E) {
    __shared__ float ce[4];
    if (threadIdx.x < 4) {
        int h = threadIdx.x;
        float s = 0.f;
#pragma unroll
        for (int d = 0; d < 32; d++) s += eW[h * 32 + d] * ae[h * 32 + d];
        ce[h] = s;
    }
    __syncthreads();
    int e = blockIdx.x * blockDim.x + threadIdx.x;
    if (e >= E) return;
    int s = src[e], d = dst[e];
    float4 ss = *(const float4*)(ssrc + (size_t)s * 4);
    float4 sd = *(const float4*)(sdst + (size_t)d * 4);
    float ea = eattr[e];
    float c0 = ss.x + sd.x + ea * ce[0];
    float c1 = ss.y + sd.y + ea * ce[1];
    float c2 = ss.z + sd.z + ea * ce[2];
    float c3 = ss.w + sd.w + ea * ce[3];
    c0 = c0 > 0.f ? c0 : 0.2f * c0;  c1 = c1 > 0.f ? c1 : 0.2f * c1;
    c2 = c2 > 0.f ? c2 : 0.2f * c2;  c3 = c3 > 0.f ? c3 : 0.2f * c3;
    float e0 = expf(c0), e1 = expf(c1), e2 = expf(c2), e3 = expf(c3);
    *(float4*)(ex + (size_t)e * 4) = make_float4(e0, e1, e2, e3);
    red_add_v4(den + (size_t)d * 4, e0, e1, e2, e3);
}

__global__ void epass12_g(const int* __restrict__ src, const int* __restrict__ dst,
                          const float* __restrict__ ssrc, const float* __restrict__ sdst,
                          float* __restrict__ ex, float* __restrict__ den, int E) {
    int e = blockIdx.x * blockDim.x + threadIdx.x;
    if (e >= E) return;
    int s = src[e], d = dst[e];
    float2 ss = *(const float2*)(ssrc + (size_t)s * 2);
    float2 sd = *(const float2*)(sdst + (size_t)d * 2);
    float c0 = ss.x + sd.x, c1 = ss.y + sd.y;
    c0 = c0 > 0.f ? c0 : 0.2f * c0;  c1 = c1 > 0.f ? c1 : 0.2f * c1;
    float e0 = expf(c0), e1 = expf(c1);
    *(float2*)(ex + (size_t)e * 2) = make_float2(e0, e1);
    red_add_v2(den + (size_t)d * 2, e0, e1);
}

// ---------------- CSR gather aggregate: residual+bias+attn-sum+ELU ----------------
// one warp per dst node; lane handles 4 channels.
template <int NH, int HD>
__global__ void gat_agg(const int* __restrict__ rowptr, const int* __restrict__ perm,
                        const int* __restrict__ src, const float* __restrict__ ex,
                        const float* __restrict__ den, const float* __restrict__ z,
                        const float* __restrict__ bias, float* __restrict__ h, int n) {
    int node = blockIdx.x * 8 + (threadIdx.x >> 5);
    if (node >= n) return;
    int lane = threadIdx.x & 31;
    int c = lane * 4;
    int head = c / HD;
    float inv = 1.f / fmaxf(den[(size_t)node * NH + head], 1e-16f);
    float4 acc = *(const float4*)(h + (size_t)node * HH + c);
    float4 bv = *(const float4*)(bias + c);
    acc.x += bv.x; acc.y += bv.y; acc.z += bv.z; acc.w += bv.w;
    int lo = rowptr[node], hi = rowptr[node + 1];
    for (int j = lo; j < hi; j++) {
        int e = perm[j];
        int s = src[e];
        float a = ex[(size_t)e * NH + head] * inv;
        float4 zv = *(const float4*)(z + (size_t)s * HH + c);
        acc.x += a * zv.x; acc.y += a * zv.y; acc.z += a * zv.z; acc.w += a * zv.w;
    }
    acc.x = acc.x > 0.f ? acc.x : expf(acc.x) - 1.f;
    acc.y = acc.y > 0.f ? acc.y : expf(acc.y) - 1.f;
    acc.z = acc.z > 0.f ? acc.z : expf(acc.z) - 1.f;
    acc.w = acc.w > 0.f ? acc.w : expf(acc.w) - 1.f;
    *(float4*)(h + (size_t)node * HH + c) = acc;
}

// ---------------- mean pooling via binary search on sorted node_batch ----------------
__global__ void pool_k(const float* __restrict__ h, const int* __restrict__ nb,
                       float* __restrict__ emb) {
    int b = blockIdx.x, t = threadIdx.x;   // 128 threads
    int lo = 0, hi = TN;
    while (lo < hi) { int mid = (lo + hi) >> 1; if (nb[mid] < b) lo = mid + 1; else hi = mid; }
    int start = lo;
    hi = TN;
    while (lo < hi) { int mid = (lo + hi) >> 1; if (nb[mid] < b + 1) lo = mid + 1; else hi = mid; }
    int end = lo;
    float s = 0.f;
    for (int i = start; i < end; i++) s += h[(size_t)i * HH + t];
    emb[(size_t)b * HH + t] = s / fmaxf((float)(end - start), 1.f);
}

// ---------------- concat [emb | gf[cid]] ----------------
__global__ void concat_k(const float* __restrict__ emb, const float* __restrict__ gf,
                         const int* __restrict__ cid, float* __restrict__ cat) {
    int i = blockIdx.x * blockDim.x + threadIdx.x;
    if (i >= BB * (HH + FGN)) return;
    int b = i / (HH + FGN), j = i % (HH + FGN);
    cat[i] = (j < HH) ? emb[(size_t)b * HH + j]
                      : gf[(size_t)cid[b] * FGN + (j - HH)];
}

// ---------------- LayerNorm(128) + ReLU ----------------
__global__ void ln_relu_k(const float* __restrict__ X, const float* __restrict__ g,
                          const float* __restrict__ be, float* __restrict__ Y) {
    int row = blockIdx.x, t = threadIdx.x;
    float v = X[(size_t)row * HH + t];
    __shared__ float red[HH];
    red[t] = v; __syncthreads();
    for (int s = 64; s > 0; s >>= 1) { if (t < s) red[t] += red[t + s]; __syncthreads(); }
    float mean = red[0] / 128.f;
    __syncthreads();
    float dv = v - mean;
    red[t] = dv * dv; __syncthreads();
    for (int s = 64; s > 0; s >>= 1) { if (t < s) red[t] += red[t + s]; __syncthreads(); }
    float var = red[0] / 128.f;
    float y = dv * rsqrtf(var + 1e-5f) * g[t] + be[t];
    Y[(size_t)row * HH + t] = fmaxf(y, 0.f);
}

// ---------------- scatter fused batch embeddings into gx ----------------
__global__ void scatfused_k(float* __restrict__ gx, const float* __restrict__ fused,
                            const int* __restrict__ cid) {
    int i = blockIdx.x * blockDim.x + threadIdx.x;
    if (i >= BB * HH) return;
    int b = i >> 7;
    gx[(size_t)cid[b] * HH + (i & 127)] = fused[i];
}

// ---------------- classifier ----------------
__global__ void classifier_k(const float* __restrict__ gx, const int* __restrict__ cid,
                             const float* __restrict__ W1, const float* __restrict__ b1,
                             const float* __restrict__ W2, const float* __restrict__ b2,
                             float* __restrict__ out) {
    int b = blockIdx.x, t = threadIdx.x;  // 64 threads
    __shared__ float row[HH];
    __shared__ float hc[HCN];
    const float* srcp = gx + (size_t)cid[b] * HH;
    row[t] = srcp[t];
    row[t + 64] = srcp[t + 64];
    __syncthreads();
    float s = b1[t];
#pragma unroll
    for (int k = 0; k < HH; k++) s += row[k] * W1[k * HCN + t];
    hc[t] = fmaxf(s, 0.f);
    __syncthreads();
    if (t < CC) {
        float s2 = b2[t];
#pragma unroll
        for (int k = 0; k < HCN; k++) s2 += hc[k] * W2[k * CC + t];
        out[b * CC + t] = s2;
    }
}

// ---------------- launch ----------------
extern "C" void kernel_launch(void* const* d_in, const int* in_sizes, int n_in,
                              void* d_out, int out_size) {
    const float* x_local    = (const float*)d_in[0];
    const float* eattr      = (const float*)d_in[1];
    const float* gfeat      = (const float*)d_in[2];
    const float* loc_in_W   = (const float*)d_in[3];
    const float* loc_in_b   = (const float*)d_in[4];
    const float* loc_W      = (const float*)d_in[5];
    const float* loc_asrc   = (const float*)d_in[6];
    const float* loc_adst   = (const float*)d_in[7];
    const float* loc_eW     = (const float*)d_in[8];
    const float* loc_ae     = (const float*)d_in[9];
    const float* loc_b      = (const float*)d_in[10];
    const float* fp_W       = (const float*)d_in[11];
    const float* fp_b       = (const float*)d_in[12];
    const float* fp_g       = (const float*)d_in[13];
    const float* fp_beta    = (const float*)d_in[14];
    const float* gp_W       = (const float*)d_in[15];
    const float* gp_b       = (const float*)d_in[16];
    const float* gp_g       = (const float*)d_in[17];
    const float* gp_beta    = (const float*)d_in[18];
    const float* glob_W     = (const float*)d_in[19];
    const float* glob_asrc  = (const float*)d_in[20];
    const float* glob_adst  = (const float*)d_in[21];
    const float* glob_b     = (const float*)d_in[22];
    const float* cls_W1     = (const float*)d_in[23];
    const float* cls_b1     = (const float*)d_in[24];
    const float* cls_W2     = (const float*)d_in[25];
    const float* cls_b2     = (const float*)d_in[26];
    const int*   eil        = (const int*)d_in[27];
    const int*   node_batch = (const int*)d_in[28];
    const int*   cid        = (const int*)d_in[29];
    const int*   gei        = (const int*)d_in[30];

    const int* lsrc = eil;
    const int* ldst = eil + ELN;
    const int* gsrc = gei;
    const int* gdst = gei + EGN;

    float *p_h, *p_z, *p_ssrc, *p_sdst, *p_esc, *p_den;
    float *p_emb, *p_cat, *p_tmp, *p_fused, *p_gx, *p_gz, *p_gesc, *p_gden;
    int *p_deg, *p_rowptr, *p_fill, *p_perm, *p_bsum;
    int *p_gdeg, *p_growptr, *p_gfill, *p_gperm, *p_gbsum;
    cudaGetSymbolAddress((void**)&p_h, g_h);
    cudaGetSymbolAddress((void**)&p_z, g_z);
    cudaGetSymbolAddress((void**)&p_ssrc, g_ssrc);
    cudaGetSymbolAddress((void**)&p_sdst, g_sdst);
    cudaGetSymbolAddress((void**)&p_esc, g_esc);
    cudaGetSymbolAddress((void**)&p_den, g_den);
    cudaGetSymbolAddress((void**)&p_emb, g_emb);
    cudaGetSymbolAddress((void**)&p_cat, g_cat);
    cudaGetSymbolAddress((void**)&p_tmp, g_tmp);
    cudaGetSymbolAddress((void**)&p_fused, g_fused);
    cudaGetSymbolAddress((void**)&p_gx, g_gx);
    cudaGetSymbolAddress((void**)&p_gz, g_gz);
    cudaGetSymbolAddress((void**)&p_gesc, g_gesc);
    cudaGetSymbolAddress((void**)&p_gden, g_gden);
    cudaGetSymbolAddress((void**)&p_deg, g_deg);
    cudaGetSymbolAddress((void**)&p_rowptr, g_rowptr);
    cudaGetSymbolAddress((void**)&p_fill, g_fill);
    cudaGetSymbolAddress((void**)&p_perm, g_perm);
    cudaGetSymbolAddress((void**)&p_bsum, g_bsum);
    cudaGetSymbolAddress((void**)&p_gdeg, g_gdeg);
    cudaGetSymbolAddress((void**)&p_growptr, g_growptr);
    cudaGetSymbolAddress((void**)&p_gfill, g_gfill);
    cudaGetSymbolAddress((void**)&p_gperm, g_gperm);
    cudaGetSymbolAddress((void**)&p_gbsum, g_gbsum);

    // ---- build CSR (dst-sorted) for both graphs ----
    cudaMemsetAsync(p_deg, 0, TN * sizeof(int));
    hist_k<<<CDIV(ELN, 256), 256>>>(ldst, p_deg, ELN);
    scan1_k<<<CDIV(TN, 1024), 256>>>(p_deg, p_bsum, TN);
    scan2_k<<<1, 32>>>(p_bsum, CDIV(TN, 1024), p_rowptr, TN, ELN);
    scan3_k<<<CDIV(TN, 1024), 256>>>(p_deg, p_bsum, p_rowptr, p_fill, TN);
    scatedge_k<<<CDIV(ELN, 256), 256>>>(ldst, p_fill, p_perm, ELN);

    cudaMemsetAsync(p_gdeg, 0, NNODE * sizeof(int));
    hist_k<<<CDIV(EGN, 256), 256>>>(gdst, p_gdeg, EGN);
    scan1_k<<<CDIV(NNODE, 1024), 256>>>(p_gdeg, p_gbsum, NNODE);
    scan2_k<<<1, 32>>>(p_gbsum, CDIV(NNODE, 1024), p_growptr, NNODE, EGN);
    scan3_k<<<CDIV(NNODE, 1024), 256>>>(p_gdeg, p_gbsum, p_growptr, p_gfill, NNODE);
    scatedge_k<<<CDIV(EGN, 256), 256>>>(gdst, p_gfill, p_gperm, EGN);

    // ---- local encoder: input projection (K=4, SIMT) ----
    gemm_tile<<<CDIV(TN, 128), 256>>>(x_local, loc_in_W, loc_in_b, p_h, TN, 4);

    // ---- 2x local GATConv ----
    for (int l = 0; l < 2; l++) {
        gemm_mma<<<CDIV(TN, 128), 256>>>(p_h, loc_W + l * HH * HH, nullptr, p_z, TN, HH);
        scores_k<4, 32><<<CDIV(TN * 4, 256), 256>>>(p_z, loc_asrc + l * HH,
                                                    loc_adst + l * HH, p_ssrc, p_sdst, TN);
        cudaMemsetAsync(p_den, 0, (size_t)TN * 4 * sizeof(float));
        epass12_l<<<CDIV(ELN, 256), 256>>>(lsrc, ldst, eattr, loc_eW + l * HH,
                                           loc_ae + l * HH, p_ssrc, p_sdst, p_esc, p_den, ELN);
        gat_agg<4, 32><<<CDIV(TN, 8), 256>>>(p_rowptr, p_perm, lsrc, p_esc, p_den,
                                             p_z, loc_b + l * HH, p_h, TN);
    }

    // ---- contract mean pooling (sorted node_batch, binary search) ----
    pool_k<<<BB, 128>>>(p_h, node_batch, p_emb);

    // ---- fused MLP ----
    concat_k<<<CDIV(BB * (HH + FGN), 256), 256>>>(p_emb, gfeat, cid, p_cat);
    gemm_mma<<<CDIV(BB, 128), 256>>>(p_cat, fp_W, fp_b, p_tmp, BB, HH + FGN);
    ln_relu_k<<<BB, HH>>>(p_tmp, fp_g, fp_beta, p_fused);

    // ---- global projection + scatter ----
    gemm_tile<<<CDIV(NNODE, 128), 256>>>(gfeat, gp_W, gp_b, p_gz, NNODE, FGN);
    ln_relu_k<<<NNODE, HH>>>(p_gz, gp_g, gp_beta, p_gx);
    scatfused_k<<<CDIV(BB * HH, 256), 256>>>(p_gx, p_fused, cid);

    // ---- 2x global GATConv ----
    for (int l = 0; l < 2; l++) {
        gemm_mma<<<CDIV(NNODE, 128), 256>>>(p_gx, glob_W + l * HH * HH, nullptr, p_gz, NNODE, HH);
        scores_k<2, 64><<<CDIV(NNODE * 2, 256), 256>>>(p_gz, glob_asrc + l * HH,
                                                       glob_adst + l * HH, p_ssrc, p_sdst, NNODE);
        cudaMemsetAsync(p_gden, 0, (size_t)NNODE * 2 * sizeof(float));
        epass12_g<<<CDIV(EGN, 256), 256>>>(gsrc, gdst, p_ssrc, p_sdst, p_gesc, p_gden, EGN);
        gat_agg<2, 64><<<CDIV(NNODE, 8), 256>>>(p_growptr, p_gperm, gsrc, p_gesc, p_gden,
                                                p_gz, glob_b + l * HH, p_gx, NNODE);
    }

    // ---- classifier ----
    classifier_k<<<BB, 64>>>(p_gx, cid, cls_W1, cls_b1, cls_W2, cls_b2, (float*)d_out);
}

// round 5
// speedup vs baseline: 3.0934x; 1.2182x over previous
#include <cuda_runtime.h>
#include <math.h>

// ---------------- problem constants ----------------
#define TN    131072     // local tx nodes
#define ELN   524288     // local edges
#define NNODE 50000      // global contract nodes
#define EGN   400000     // global edges
#define BB    8192       // batch of contracts
#define HH    128        // hidden dim
#define FGN   7          // global feat dim
#define HCN   64         // classifier hidden
#define CC    2          // classes

#define CDIV(a,b) (((a)+(b)-1)/(b))

// ---------------- scratch (device globals) ----------------
__device__ float g_h   [TN*HH];
__device__ float g_z   [TN*HH];
__device__ float g_ssrc[TN*4];
__device__ float g_sdst[TN*4];
__device__ float g_emb [BB*HH];
__device__ float g_cat [BB*(HH+FGN)];
__device__ float g_tmp [BB*HH];
__device__ float g_fused[BB*HH];
__device__ float g_gx  [NNODE*HH];
__device__ float g_gz  [NNODE*HH];
// CSR scratch
__device__ int   g_deg   [TN];
__device__ int   g_rowptr[TN+1];
__device__ int   g_fill  [TN];
__device__ int   g_psrc  [ELN];
__device__ float g_pea   [ELN];
__device__ int   g_bsum  [256];
__device__ int   g_gdeg   [NNODE];
__device__ int   g_growptr[NNODE+1];
__device__ int   g_gfill  [NNODE];
__device__ int   g_gpsrc  [EGN];
__device__ int   g_gbsum  [256];

// ---------------- helpers ----------------
__device__ __forceinline__ unsigned f2tf32(float f) {
    unsigned r;
    asm("cvt.rna.tf32.f32 %0, %1;" : "=r"(r) : "f"(f));
    return r;
}

// ================= CSR construction =================
__global__ void hist_k(const int* __restrict__ dst, int* __restrict__ deg, int E) {
    int e = blockIdx.x * blockDim.x + threadIdx.x;
    if (e < E) atomicAdd(&deg[dst[e]], 1);
}
__global__ void scan1_k(const int* __restrict__ deg, int* __restrict__ bsum, int n) {
    __shared__ int s[256];
    int base = blockIdx.x * 1024, t = threadIdx.x;
    int sum = 0;
#pragma unroll
    for (int i = 0; i < 4; i++) {
        int idx = base + t * 4 + i;
        if (idx < n) sum += deg[idx];
    }
    s[t] = sum; __syncthreads();
    for (int o = 128; o > 0; o >>= 1) { if (t < o) s[t] += s[t + o]; __syncthreads(); }
    if (t == 0) bsum[blockIdx.x] = s[0];
}
__global__ void scan2_k(int* __restrict__ bsum, int nb, int* __restrict__ rowptr,
                        int n, int E) {
    if (threadIdx.x == 0) {
        int acc = 0;
        for (int i = 0; i < nb; i++) { int v = bsum[i]; bsum[i] = acc; acc += v; }
        rowptr[n] = E;
    }
}
__global__ void scan3_k(const int* __restrict__ deg, const int* __restrict__ bsum,
                        int* __restrict__ rowptr, int* __restrict__ fill, int n) {
    __shared__ int s[256];
    int base = blockIdx.x * 1024, t = threadIdx.x;
    int v[4]; int sum = 0;
#pragma unroll
    for (int i = 0; i < 4; i++) {
        int idx = base + t * 4 + i;
        v[i] = (idx < n) ? deg[idx] : 0;
        sum += v[i];
    }
    s[t] = sum; __syncthreads();
    for (int o = 1; o < 256; o <<= 1) {
        int x = (t >= o) ? s[t - o] : 0;
        __syncthreads();
        s[t] += x;
        __syncthreads();
    }
    int excl = ((t == 0) ? 0 : s[t - 1]) + bsum[blockIdx.x];
#pragma unroll
    for (int i = 0; i < 4; i++) {
        int idx = base + t * 4 + i;
        if (idx < n) { rowptr[idx] = excl; fill[idx] = excl; }
        excl += v[i];
    }
}
// scatter edges: store permuted src (and optionally permuted edge attr)
__global__ void scatedge_k(const int* __restrict__ src, const int* __restrict__ dst,
                           const float* __restrict__ eattr, int* __restrict__ fill,
                           int* __restrict__ psrc, float* __restrict__ pea, int E) {
    int e = blockIdx.x * blockDim.x + threadIdx.x;
    if (e < E) {
        int p = atomicAdd(&fill[dst[e]], 1);
        psrc[p] = src[e];
        if (pea) pea[p] = eattr[e];
    }
}

// ================= tf32 MMA GEMM =================
#define A_PAD 36
#define W_PAD 136
__global__ __launch_bounds__(256, 2)
void gemm_mma(const float* __restrict__ A, const float* __restrict__ W,
              const float* __restrict__ bias, float* __restrict__ C,
              int M, int K) {
    __shared__ unsigned As[128 * A_PAD];
    __shared__ unsigned Ws[32 * W_PAD];
    const int tid  = threadIdx.x;
    const int warp = tid >> 5, lane = tid & 31;
    const int bm   = blockIdx.x * 128;
    const int wm   = (warp >> 1) * 32;
    const int wn   = (warp & 1) * 64;
    const int g    = lane >> 2;
    const int ct   = lane & 3;

    float c[2][8][4];
#pragma unroll
    for (int mt = 0; mt < 2; mt++)
#pragma unroll
        for (int nt = 0; nt < 8; nt++)
#pragma unroll
            for (int r = 0; r < 4; r++) c[mt][nt][r] = 0.f;

    for (int k0 = 0; k0 < K; k0 += 32) {
#pragma unroll
        for (int i = tid; i < 128 * 32; i += 256) {
            int m = i >> 5, k = i & 31;
            int gr = bm + m, gk = k0 + k;
            float v = (gr < M && gk < K) ? A[(size_t)gr * K + gk] : 0.f;
            As[m * A_PAD + k] = f2tf32(v);
        }
#pragma unroll
        for (int i = tid; i < 32 * 128; i += 256) {
            int k = i >> 7, n = i & 127;
            int gk = k0 + k;
            float v = (gk < K) ? W[gk * 128 + n] : 0.f;
            Ws[k * W_PAD + n] = f2tf32(v);
        }
        __syncthreads();
#pragma unroll
        for (int ks = 0; ks < 32; ks += 8) {
            unsigned b[8][2];
#pragma unroll
            for (int nt = 0; nt < 8; nt++) {
                int n = wn + nt * 8 + g;
                b[nt][0] = Ws[(ks + ct) * W_PAD + n];
                b[nt][1] = Ws[(ks + ct + 4) * W_PAD + n];
            }
#pragma unroll
            for (int mt = 0; mt < 2; mt++) {
                int r0 = wm + mt * 16 + g;
                unsigned a0 = As[r0 * A_PAD + ks + ct];
                unsigned a1 = As[(r0 + 8) * A_PAD + ks + ct];
                unsigned a2 = As[r0 * A_PAD + ks + ct + 4];
                unsigned a3 = As[(r0 + 8) * A_PAD + ks + ct + 4];
#pragma unroll
                for (int nt = 0; nt < 8; nt++) {
                    asm volatile(
                        "mma.sync.aligned.m16n8k8.row.col.f32.tf32.tf32.f32 "
                        "{%0,%1,%2,%3}, {%4,%5,%6,%7}, {%8,%9}, {%0,%1,%2,%3};"
                        : "+f"(c[mt][nt][0]), "+f"(c[mt][nt][1]),
                          "+f"(c[mt][nt][2]), "+f"(c[mt][nt][3])
                        : "r"(a0), "r"(a1), "r"(a2), "r"(a3),
                          "r"(b[nt][0]), "r"(b[nt][1]));
                }
            }
        }
        __syncthreads();
    }
#pragma unroll
    for (int mt = 0; mt < 2; mt++) {
        int row0 = bm + wm + mt * 16 + g;
        int row1 = row0 + 8;
#pragma unroll
        for (int nt = 0; nt < 8; nt++) {
            int col = wn + nt * 8 + 2 * ct;
            float b0 = bias ? bias[col] : 0.f;
            float b1 = bias ? bias[col + 1] : 0.f;
            if (row0 < M)
                *(float2*)(C + (size_t)row0 * 128 + col) =
                    make_float2(c[mt][nt][0] + b0, c[mt][nt][1] + b1);
            if (row1 < M)
                *(float2*)(C + (size_t)row1 * 128 + col) =
                    make_float2(c[mt][nt][2] + b0, c[mt][nt][3] + b1);
        }
    }
}

// ---------------- SIMT GEMM for tiny-K projections ----------------
__global__ __launch_bounds__(256, 2)
void gemm_tile(const float* __restrict__ A, const float* __restrict__ W,
               const float* __restrict__ bias, float* __restrict__ C,
               int M, int K) {
    __shared__ float As[16 * 132];
    __shared__ float Ws[16 * 132];
    const int bm  = blockIdx.x * 128;
    const int tid = threadIdx.x;
    const int tr  = (tid >> 4) * 8;
    const int tc  = (tid & 15) * 8;
    float acc[8][8];
#pragma unroll
    for (int x = 0; x < 8; x++)
#pragma unroll
        for (int y = 0; y < 8; y++) acc[x][y] = 0.f;

    for (int k0 = 0; k0 < K; k0 += 16) {
        for (int i = tid; i < 128 * 16; i += 256) {
            int m = i >> 4, kk = i & 15;
            int gr = bm + m, gk = k0 + kk;
            As[kk * 132 + m] = (gr < M && gk < K) ? A[(size_t)gr * K + gk] : 0.f;
        }
        for (int i = tid; i < 16 * 128; i += 256) {
            int kk = i >> 7, n = i & 127;
            int gk = k0 + kk;
            Ws[kk * 132 + n] = (gk < K) ? W[gk * 128 + n] : 0.f;
        }
        __syncthreads();
#pragma unroll
        for (int kk = 0; kk < 16; kk++) {
            float a[8], w[8];
#pragma unroll
            for (int x = 0; x < 8; x++) a[x] = As[kk * 132 + tr + x];
#pragma unroll
            for (int y = 0; y < 8; y++) w[y] = Ws[kk * 132 + tc + y];
#pragma unroll
            for (int x = 0; x < 8; x++)
#pragma unroll
                for (int y = 0; y < 8; y++) acc[x][y] += a[x] * w[y];
        }
        __syncthreads();
    }
#pragma unroll
    for (int x = 0; x < 8; x++) {
        int gr = bm + tr + x;
        if (gr < M) {
#pragma unroll
            for (int y = 0; y < 8; y++) {
                float v = acc[x][y];
                if (bias) v += bias[tc + y];
                C[(size_t)gr * 128 + tc + y] = v;
            }
        }
    }
}

// ---------------- per-node attention scores (float4 loads) ----------------
template <int NH, int HD>
__global__ void scores_k(const float* __restrict__ z, const float* __restrict__ as_,
                         const float* __restrict__ ad_, float* __restrict__ ssrc,
                         float* __restrict__ sdst, int n) {
    int i = blockIdx.x * blockDim.x + threadIdx.x;
    if (i >= n * NH) return;
    int node = i / NH, h = i % NH;
    const float4* zp = (const float4*)(z + (size_t)node * HH + h * HD);
    const float4* ap = (const float4*)(as_ + h * HD);
    const float4* dp = (const float4*)(ad_ + h * HD);
    float s = 0.f, t = 0.f;
#pragma unroll
    for (int d = 0; d < HD / 4; d++) {
        float4 zv = zp[d], av = ap[d], dv = dp[d];
        s += zv.x * av.x + zv.y * av.y + zv.z * av.z + zv.w * av.w;
        t += zv.x * dv.x + zv.y * dv.y + zv.z * dv.z + zv.w * dv.w;
    }
    ssrc[i] = s; sdst[i] = t;
}

// ---------------- fused single-pass GAT aggregation ----------------
// warp per dst node, lane = 4 channels. Computes per-edge score inline,
// accumulates unnormalized weighted sum + denominator, normalizes at end,
// then residual + bias + ELU. No atomics, no edge-score buffer.
template <int NH, int HD, bool HAS_E>
__global__ void gat_fused(const int* __restrict__ rowptr, const int* __restrict__ psrc,
                          const float* __restrict__ pea,
                          const float* __restrict__ eW, const float* __restrict__ ae,
                          const float* __restrict__ ssrc, const float* __restrict__ sdst,
                          const float* __restrict__ z, const float* __restrict__ bias,
                          float* __restrict__ h, int n) {
    __shared__ float ce_s[NH];
    if (HAS_E && threadIdx.x < NH) {
        int hh = threadIdx.x;
        float s = 0.f;
#pragma unroll
        for (int d = 0; d < HD; d++) s += eW[hh * HD + d] * ae[hh * HD + d];
        ce_s[hh] = s;
    }
    if (HAS_E) __syncthreads();

    int node = blockIdx.x * 8 + (threadIdx.x >> 5);
    if (node >= n) return;
    int lane = threadIdx.x & 31;
    int c = lane * 4;
    int head = c / HD;

    float sd = sdst[(size_t)node * NH + head];
    float ce = HAS_E ? ce_s[head] : 0.f;

    float4 acc = make_float4(0.f, 0.f, 0.f, 0.f);
    float den = 0.f;
    int lo = rowptr[node], hi = rowptr[node + 1];
    for (int j = lo; j < hi; j++) {
        int s = psrc[j];
        float sc = ssrc[(size_t)s * NH + head] + sd;
        if (HAS_E) sc += pea[j] * ce;
        sc = sc > 0.f ? sc : 0.2f * sc;
        float ex = __expf(sc);
        den += ex;
        float4 zv = *(const float4*)(z + (size_t)s * HH + c);
        acc.x += ex * zv.x; acc.y += ex * zv.y;
        acc.z += ex * zv.z; acc.w += ex * zv.w;
    }
    float inv = 1.f / fmaxf(den, 1e-16f);
    float4 hv = *(const float4*)(h + (size_t)node * HH + c);
    float4 bv = *(const float4*)(bias + c);
    acc.x = hv.x + bv.x + acc.x * inv;
    acc.y = hv.y + bv.y + acc.y * inv;
    acc.z = hv.z + bv.z + acc.z * inv;
    acc.w = hv.w + bv.w + acc.w * inv;
    acc.x = acc.x > 0.f ? acc.x : expf(acc.x) - 1.f;
    acc.y = acc.y > 0.f ? acc.y : expf(acc.y) - 1.f;
    acc.z = acc.z > 0.f ? acc.z : expf(acc.z) - 1.f;
    acc.w = acc.w > 0.f ? acc.w : expf(acc.w) - 1.f;
    *(float4*)(h + (size_t)node * HH + c) = acc;
}

// ---------------- mean pooling via binary search on sorted node_batch ----------------
__global__ void pool_k(const float* __restrict__ h, const int* __restrict__ nb,
                       float* __restrict__ emb) {
    int b = blockIdx.x, t = threadIdx.x;   // 128 threads
    int lo = 0, hi = TN;
    while (lo < hi) { int mid = (lo + hi) >> 1; if (nb[mid] < b) lo = mid + 1; else hi = mid; }
    int start = lo;
    hi = TN;
    while (lo < hi) { int mid = (lo + hi) >> 1; if (nb[mid] < b + 1) lo = mid + 1; else hi = mid; }
    int end = lo;
    float s = 0.f;
    for (int i = start; i < end; i++) s += h[(size_t)i * HH + t];
    emb[(size_t)b * HH + t] = s / fmaxf((float)(end - start), 1.f);
}

// ---------------- concat [emb | gf[cid]] ----------------
__global__ void concat_k(const float* __restrict__ emb, const float* __restrict__ gf,
                         const int* __restrict__ cid, float* __restrict__ cat) {
    int i = blockIdx.x * blockDim.x + threadIdx.x;
    if (i >= BB * (HH + FGN)) return;
    int b = i / (HH + FGN), j = i % (HH + FGN);
    cat[i] = (j < HH) ? emb[(size_t)b * HH + j]
                      : gf[(size_t)cid[b] * FGN + (j - HH)];
}

// ---------------- LayerNorm(128) + ReLU ----------------
__global__ void ln_relu_k(const float* __restrict__ X, const float* __restrict__ g,
                          const float* __restrict__ be, float* __restrict__ Y) {
    int row = blockIdx.x, t = threadIdx.x;
    float v = X[(size_t)row * HH + t];
    __shared__ float red[HH];
    red[t] = v; __syncthreads();
    for (int s = 64; s > 0; s >>= 1) { if (t < s) red[t] += red[t + s]; __syncthreads(); }
    float mean = red[0] / 128.f;
    __syncthreads();
    float dv = v - mean;
    red[t] = dv * dv; __syncthreads();
    for (int s = 64; s > 0; s >>= 1) { if (t < s) red[t] += red[t + s]; __syncthreads(); }
    float var = red[0] / 128.f;
    float y = dv * rsqrtf(var + 1e-5f) * g[t] + be[t];
    Y[(size_t)row * HH + t] = fmaxf(y, 0.f);
}

// ---------------- scatter fused batch embeddings into gx ----------------
__global__ void scatfused_k(float* __restrict__ gx, const float* __restrict__ fused,
                            const int* __restrict__ cid) {
    int i = blockIdx.x * blockDim.x + threadIdx.x;
    if (i >= BB * HH) return;
    int b = i >> 7;
    gx[(size_t)cid[b] * HH + (i & 127)] = fused[i];
}

// ---------------- classifier ----------------
__global__ void classifier_k(const float* __restrict__ gx, const int* __restrict__ cid,
                             const float* __restrict__ W1, const float* __restrict__ b1,
                             const float* __restrict__ W2, const float* __restrict__ b2,
                             float* __restrict__ out) {
    int b = blockIdx.x, t = threadIdx.x;  // 64 threads
    __shared__ float row[HH];
    __shared__ float hc[HCN];
    const float* srcp = gx + (size_t)cid[b] * HH;
    row[t] = srcp[t];
    row[t + 64] = srcp[t + 64];
    __syncthreads();
    float s = b1[t];
#pragma unroll
    for (int k = 0; k < HH; k++) s += row[k] * W1[k * HCN + t];
    hc[t] = fmaxf(s, 0.f);
    __syncthreads();
    if (t < CC) {
        float s2 = b2[t];
#pragma unroll
        for (int k = 0; k < HCN; k++) s2 += hc[k] * W2[k * CC + t];
        out[b * CC + t] = s2;
    }
}

// ---------------- launch ----------------
extern "C" void kernel_launch(void* const* d_in, const int* in_sizes, int n_in,
                              void* d_out, int out_size) {
    const float* x_local    = (const float*)d_in[0];
    const float* eattr      = (const float*)d_in[1];
    const float* gfeat      = (const float*)d_in[2];
    const float* loc_in_W   = (const float*)d_in[3];
    const float* loc_in_b   = (const float*)d_in[4];
    const float* loc_W      = (const float*)d_in[5];
    const float* loc_asrc   = (const float*)d_in[6];
    const float* loc_adst   = (const float*)d_in[7];
    const float* loc_eW     = (const float*)d_in[8];
    const float* loc_ae     = (const float*)d_in[9];
    const float* loc_b      = (const float*)d_in[10];
    const float* fp_W       = (const float*)d_in[11];
    const float* fp_b       = (const float*)d_in[12];
    const float* fp_g       = (const float*)d_in[13];
    const float* fp_beta    = (const float*)d_in[14];
    const float* gp_W       = (const float*)d_in[15];
    const float* gp_b       = (const float*)d_in[16];
    const float* gp_g       = (const float*)d_in[17];
    const float* gp_beta    = (const float*)d_in[18];
    const float* glob_W     = (const float*)d_in[19];
    const float* glob_asrc  = (const float*)d_in[20];
    const float* glob_adst  = (const float*)d_in[21];
    const float* glob_b     = (const float*)d_in[22];
    const float* cls_W1     = (const float*)d_in[23];
    const float* cls_b1     = (const float*)d_in[24];
    const float* cls_W2     = (const float*)d_in[25];
    const float* cls_b2     = (const float*)d_in[26];
    const int*   eil        = (const int*)d_in[27];
    const int*   node_batch = (const int*)d_in[28];
    const int*   cid        = (const int*)d_in[29];
    const int*   gei        = (const int*)d_in[30];

    const int* lsrc = eil;
    const int* ldst = eil + ELN;
    const int* gsrc = gei;
    const int* gdst = gei + EGN;

    float *p_h, *p_z, *p_ssrc, *p_sdst;
    float *p_emb, *p_cat, *p_tmp, *p_fused, *p_gx, *p_gz, *p_pea;
    int *p_deg, *p_rowptr, *p_fill, *p_psrc, *p_bsum;
    int *p_gdeg, *p_growptr, *p_gfill, *p_gpsrc, *p_gbsum;
    cudaGetSymbolAddress((void**)&p_h, g_h);
    cudaGetSymbolAddress((void**)&p_z, g_z);
    cudaGetSymbolAddress((void**)&p_ssrc, g_ssrc);
    cudaGetSymbolAddress((void**)&p_sdst, g_sdst);
    cudaGetSymbolAddress((void**)&p_emb, g_emb);
    cudaGetSymbolAddress((void**)&p_cat, g_cat);
    cudaGetSymbolAddress((void**)&p_tmp, g_tmp);
    cudaGetSymbolAddress((void**)&p_fused, g_fused);
    cudaGetSymbolAddress((void**)&p_gx, g_gx);
    cudaGetSymbolAddress((void**)&p_gz, g_gz);
    cudaGetSymbolAddress((void**)&p_pea, g_pea);
    cudaGetSymbolAddress((void**)&p_deg, g_deg);
    cudaGetSymbolAddress((void**)&p_rowptr, g_rowptr);
    cudaGetSymbolAddress((void**)&p_fill, g_fill);
    cudaGetSymbolAddress((void**)&p_psrc, g_psrc);
    cudaGetSymbolAddress((void**)&p_bsum, g_bsum);
    cudaGetSymbolAddress((void**)&p_gdeg, g_gdeg);
    cudaGetSymbolAddress((void**)&p_growptr, g_growptr);
    cudaGetSymbolAddress((void**)&p_gfill, g_gfill);
    cudaGetSymbolAddress((void**)&p_gpsrc, g_gpsrc);
    cudaGetSymbolAddress((void**)&p_gbsum, g_gbsum);

    // ---- build CSR (dst-sorted, pre-permuted payloads) ----
    cudaMemsetAsync(p_deg, 0, TN * sizeof(int));
    hist_k<<<CDIV(ELN, 256), 256>>>(ldst, p_deg, ELN);
    scan1_k<<<CDIV(TN, 1024), 256>>>(p_deg, p_bsum, TN);
    scan2_k<<<1, 32>>>(p_bsum, CDIV(TN, 1024), p_rowptr, TN, ELN);
    scan3_k<<<CDIV(TN, 1024), 256>>>(p_deg, p_bsum, p_rowptr, p_fill, TN);
    scatedge_k<<<CDIV(ELN, 256), 256>>>(lsrc, ldst, eattr, p_fill, p_psrc, p_pea, ELN);

    cudaMemsetAsync(p_gdeg, 0, NNODE * sizeof(int));
    hist_k<<<CDIV(EGN, 256), 256>>>(gdst, p_gdeg, EGN);
    scan1_k<<<CDIV(NNODE, 1024), 256>>>(p_gdeg, p_gbsum, NNODE);
    scan2_k<<<1, 32>>>(p_gbsum, CDIV(NNODE, 1024), p_growptr, NNODE, EGN);
    scan3_k<<<CDIV(NNODE, 1024), 256>>>(p_gdeg, p_gbsum, p_growptr, p_gfill, NNODE);
    scatedge_k<<<CDIV(EGN, 256), 256>>>(gsrc, gdst, (const float*)nullptr, p_gfill,
                                        p_gpsrc, (float*)nullptr, EGN);

    // ---- local encoder: input projection (K=4, SIMT) ----
    gemm_tile<<<CDIV(TN, 128), 256>>>(x_local, loc_in_W, loc_in_b, p_h, TN, 4);

    // ---- 2x local GATConv (fused single-pass aggregation) ----
    for (int l = 0; l < 2; l++) {
        gemm_mma<<<CDIV(TN, 128), 256>>>(p_h, loc_W + l * HH * HH, nullptr, p_z, TN, HH);
        scores_k<4, 32><<<CDIV(TN * 4, 256), 256>>>(p_z, loc_asrc + l * HH,
                                                    loc_adst + l * HH, p_ssrc, p_sdst, TN);
        gat_fused<4, 32, true><<<CDIV(TN, 8), 256>>>(p_rowptr, p_psrc, p_pea,
                                                     loc_eW + l * HH, loc_ae + l * HH,
                                                     p_ssrc, p_sdst, p_z,
                                                     loc_b + l * HH, p_h, TN);
    }

    // ---- contract mean pooling ----
    pool_k<<<BB, 128>>>(p_h, node_batch, p_emb);

    // ---- fused MLP ----
    concat_k<<<CDIV(BB * (HH + FGN), 256), 256>>>(p_emb, gfeat, cid, p_cat);
    gemm_mma<<<CDIV(BB, 128), 256>>>(p_cat, fp_W, fp_b, p_tmp, BB, HH + FGN);
    ln_relu_k<<<BB, HH>>>(p_tmp, fp_g, fp_beta, p_fused);

    // ---- global projection + scatter ----
    gemm_tile<<<CDIV(NNODE, 128), 256>>>(gfeat, gp_W, gp_b, p_gz, NNODE, FGN);
    ln_relu_k<<<NNODE, HH>>>(p_gz, gp_g, gp_beta, p_gx);
    scatfused_k<<<CDIV(BB * HH, 256), 256>>>(p_gx, p_fused, cid);

    // ---- 2x global GATConv ----
    for (int l = 0; l < 2; l++) {
        gemm_mma<<<CDIV(NNODE, 128), 256>>>(p_gx, glob_W + l * HH * HH, nullptr, p_gz, NNODE, HH);
        scores_k<2, 64><<<CDIV(NNODE * 2, 256), 256>>>(p_gz, glob_asrc + l * HH,
                                                       glob_adst + l * HH, p_ssrc, p_sdst, NNODE);
        gat_fused<2, 64, false><<<CDIV(NNODE, 8), 256>>>(p_growptr, p_gpsrc, (float*)nullptr,
                                                         (float*)nullptr, (float*)nullptr,
                                                         p_ssrc, p_sdst, p_gz,
                                                         glob_b + l * HH, p_gx, NNODE);
    }

    // ---- classifier ----
    classifier_k<<<BB, 64>>>(p_gx, cid, cls_W1, cls_b1, cls_W2, cls_b2, (float*)d_out);
}